// round 14
// baseline (speedup 1.0000x reference)
#include <cuda_runtime.h>
#include <cuda_bf16.h>
#include <cuda_fp16.h>
#include <cstdint>

#define S 2048
#define D 4096
#define H 32
#define KVH 8
#define HD 128
#define NREP (H / KVH)
#define KVD (KVH * HD)
#define PGRID 304

// ---------------- scratch (static device arrays; no allocation) ----------------
__device__ __half g_x16h[S * D], g_x16l[S * D];
__device__ __half g_a16[S * D];
__device__ __half g_q16h[S * D], g_q16l[S * D];
__device__ __half g_k16h[S * KVD], g_k16l[S * KVD];
__device__ __half g_vt16[KVD * S];                 // transposed [KVD][S]
__device__ __half g_wq16[D * D];                   // transposed [N,K]
__device__ __half g_wk16[KVD * D];
__device__ __half g_wv16[KVD * D];
__device__ __half g_wo16[D * D];
__device__ int    g_ctr;
__device__ int    g_ctr2;

// ---------------- helpers ----------------
__device__ __forceinline__ uint32_t s2u(const void* p) {
    uint32_t a;
    asm("{ .reg .u64 t; cvta.to.shared.u64 t, %1; cvt.u32.u64 %0, t; }" : "=r"(a) : "l"(p));
    return a;
}
__device__ __forceinline__ void cpasync16(uint32_t saddr, const void* gaddr) {
    asm volatile("cp.async.cg.shared.global [%0], [%1], 16;" :: "r"(saddr), "l"(gaddr));
}
__device__ __forceinline__ void ldmx4(uint32_t* r, uint32_t addr) {
    asm volatile("ldmatrix.sync.aligned.m8n8.x4.shared.b16 {%0,%1,%2,%3}, [%4];"
                 : "=r"(r[0]), "=r"(r[1]), "=r"(r[2]), "=r"(r[3]) : "r"(addr));
}
__device__ __forceinline__ void mma16816h(float* d, const uint32_t* a, const uint32_t* b) {
    asm volatile(
        "mma.sync.aligned.m16n8k16.row.col.f32.f16.f16.f32 "
        "{%0,%1,%2,%3}, {%4,%5,%6,%7}, {%8,%9}, {%0,%1,%2,%3};"
        : "+f"(d[0]), "+f"(d[1]), "+f"(d[2]), "+f"(d[3])
        : "r"(a[0]), "r"(a[1]), "r"(a[2]), "r"(a[3]), "r"(b[0]), "r"(b[1]));
}
__device__ __forceinline__ uint32_t pack_f16(float x, float y) {
    __half2 t = __floats2half2_rn(x, y);
    return *reinterpret_cast<uint32_t*>(&t);
}
__device__ __forceinline__ void split2h(float v0, float v1, __half2& ph, __half2& pl) {
    __half h0 = __float2half_rn(v0), h1 = __float2half_rn(v1);
    ph = __halves2half2(h0, h1);
    pl = __halves2half2(__float2half_rn(v0 - __half2float(h0)),
                        __float2half_rn(v1 - __half2float(h1)));
}

// ---------------- counter reset (both) ----------------
__global__ void reset_ctr() { g_ctr = 0; g_ctr2 = 0; }

// ---------------- x: fp32 -> fp16 hi/lo ----------------
__global__ void xsplit16(const float* __restrict__ in,
                         __half* __restrict__ fh, __half* __restrict__ fl, int n4)
{
    int i = blockIdx.x * blockDim.x + threadIdx.x;
    if (i >= n4) return;
    float4 v = reinterpret_cast<const float4*>(in)[i];
    __half2 hh, hl;
    split2h(v.x, v.y, hh, hl);
    reinterpret_cast<__half2*>(fh)[2 * i] = hh;
    reinterpret_cast<__half2*>(fl)[2 * i] = hl;
    split2h(v.z, v.w, hh, hl);
    reinterpret_cast<__half2*>(fh)[2 * i + 1] = hh;
    reinterpret_cast<__half2*>(fl)[2 * i + 1] = hl;
}

// ---------------- transpose: W[K,N] fp32 -> fp16 [N,K], half2 writes ----------------
__global__ void tsplit16_kernel(const float* __restrict__ w,
                                __half* __restrict__ out, int K, int N)
{
    __shared__ float t[64][33];
    int n0 = blockIdx.x * 32, k0 = blockIdx.y * 64;
    int tx = threadIdx.x, ty = threadIdx.y;   // (32, 8)
    for (int r = ty; r < 64; r += 8)
        t[r][tx] = w[(size_t)(k0 + r) * N + n0 + tx];
    __syncthreads();
    for (int nn = ty; nn < 32; nn += 8) {
        __half2 h = __floats2half2_rn(t[2 * tx][nn], t[2 * tx + 1][nn]);
        *reinterpret_cast<__half2*>(out + (size_t)(n0 + nn) * K + k0 + 2 * tx) = h;
    }
}

#define GTILE  8192u
#define GSTAGE 24576u   // 3 tiles: A-hi, A-lo, B

// tile map: [0,128) K tiles, [128,640) Q tiles, [640,768) V tiles (1-term, light)
#define NT_K 128
#define NT_Q 512
#define NT_TOT 768

// ---------------- unified persistent projection kernel (all fp16) ----------------
__global__ __launch_bounds__(256, 2) void proj_kernel(
    const __half* __restrict__ X16h, const __half* __restrict__ X16l,
    const __half* __restrict__ Wq16, const __half* __restrict__ Wk16,
    const __half* __restrict__ Wv16,
    __half* __restrict__ Q16h, __half* __restrict__ Q16l,
    __half* __restrict__ K16h, __half* __restrict__ K16l,
    __half* __restrict__ Vt16,
    const float* __restrict__ cosb, const float* __restrict__ sinb, float qscale)
{
    extern __shared__ char dsm[];
    const uint32_t smem = s2u(dsm);
    __shared__ int s_tile;

    const int tid = threadIdx.x;
    const int wid = tid >> 5;
    const int lane = tid & 31;
    const int wm = (wid & 1) * 64;
    const int wn = (wid >> 1) * 32;
    const int grp = lane >> 3;
    const int ri = lane & 7;
    const int erow = lane >> 2;
    const int ecol = (lane & 3) * 2;
    const int nchunks = D >> 5;

    while (true) {
        __syncthreads();
        if (tid == 0) s_tile = atomicAdd(&g_ctr, 1);
        __syncthreads();
        const int t = s_tile;
        if (t >= NT_TOT) break;

        const bool isV = (t >= NT_K + NT_Q);
        const __half* B;
        __half *Ch = nullptr, *Cl = nullptr;
        int bx, by, Ndim = 0;
        float scale = 1.0f;
        if (t < NT_K) {
            B = Wk16; bx = (t & 7) * 128; by = (t >> 3) * 128;
            Ndim = KVD; Ch = K16h; Cl = K16l;
        } else if (!isV) {
            int q = t - NT_K;
            B = Wq16; bx = (q & 31) * 128; by = (q >> 5) * 128;
            Ndim = D; scale = qscale; Ch = Q16h; Cl = Q16l;
        } else {
            int v = t - NT_K - NT_Q;
            B = Wv16; bx = (v & 7) * 128; by = (v >> 3) * 128;
        }
        const bool two_term = !isV;

        float acc[4][4][4];
#pragma unroll
        for (int i = 0; i < 4; i++)
#pragma unroll
            for (int j = 0; j < 4; j++)
#pragma unroll
                for (int e = 0; e < 4; e++) acc[i][j][e] = 0.0f;

        auto load_stage = [&](int c, int stage) {
            const uint32_t sb = smem + stage * GSTAGE;
            const int k0 = c << 5;
#pragma unroll
            for (int i = 0; i < 2; i++) {
                int idx = tid + i * 256;
                int row = idx >> 2, cc = idx & 3;
                uint32_t sc = (uint32_t)(cc ^ ((row >> 1) & 3));
                uint32_t so = (uint32_t)row * 64u + sc * 16u;
                size_t ga = (size_t)(by + row) * D + k0 + cc * 8;
                cpasync16(sb + so, X16h + ga);
                if (two_term) cpasync16(sb + GTILE + so, X16l + ga);
                cpasync16(sb + 2 * GTILE + so, B + (size_t)(bx + row) * D + k0 + cc * 8);
            }
        };

        load_stage(0, 0);
        asm volatile("cp.async.commit_group;");
        load_stage(1, 1);
        asm volatile("cp.async.commit_group;");

        for (int c = 0; c < nchunks; c++) {
            if (c + 1 < nchunks) asm volatile("cp.async.wait_group 1;");
            else                 asm volatile("cp.async.wait_group 0;");
            __syncthreads();
            if (c + 2 < nchunks) {
                load_stage(c + 2, (c + 2) % 3);
                asm volatile("cp.async.commit_group;");
            }
            const uint32_t sb = smem + (c % 3) * GSTAGE;

#pragma unroll
            for (int k16 = 0; k16 < 2; k16++) {
                const int lchunk = k16 * 2 + (grp >> 1);
                uint32_t ah[4][4], al[4][4];
#pragma unroll
                for (int fm = 0; fm < 4; fm++) {
                    int row = wm + fm * 16 + (grp & 1) * 8 + ri;
                    uint32_t ad = sb + (uint32_t)row * 64u
                                + (uint32_t)((lchunk ^ ((row >> 1) & 3)) * 16);
                    ldmx4(ah[fm], ad);
                    if (two_term) ldmx4(al[fm], ad + GTILE);
                }
#pragma unroll
                for (int fnp = 0; fnp < 2; fnp++) {
                    int row = wn + fnp * 16 + (grp & 1) * 8 + ri;
                    uint32_t bd = sb + 2 * GTILE + (uint32_t)row * 64u
                                + (uint32_t)((lchunk ^ ((row >> 1) & 3)) * 16);
                    uint32_t bh4[4];
                    ldmx4(bh4, bd);
                    uint32_t be[2] = {bh4[0], bh4[2]};
                    uint32_t bo[2] = {bh4[1], bh4[3]};
#pragma unroll
                    for (int fm = 0; fm < 4; fm++) {
                        mma16816h(acc[fm][2 * fnp],     ah[fm], be);
                        mma16816h(acc[fm][2 * fnp + 1], ah[fm], bo);
                        if (two_term) {
                            mma16816h(acc[fm][2 * fnp],     al[fm], be);
                            mma16816h(acc[fm][2 * fnp + 1], al[fm], bo);
                        }
                    }
                }
            }
        }

        if (!isV) {
            // RoPE + scale + fp16 split
#pragma unroll
            for (int fm = 0; fm < 4; fm++) {
#pragma unroll
                for (int fn = 0; fn < 4; fn++) {
                    int col = bx + wn + fn * 8 + ecol;
                    int i = (col & 127) >> 1;
#pragma unroll
                    for (int half = 0; half < 2; half++) {
                        int row = by + wm + fm * 16 + erow + half * 8;
                        float cv = cosb[row * 64 + i];
                        float sv = sinb[row * 64 + i];
                        float t0 = acc[fm][fn][half * 2], t1 = acc[fm][fn][half * 2 + 1];
                        float o0 = (t0 * cv - t1 * sv) * scale;
                        float o1 = (t0 * sv + t1 * cv) * scale;
                        __half2 ph, pl;
                        split2h(o0, o1, ph, pl);
                        size_t o = (size_t)row * Ndim + col;
                        *reinterpret_cast<__half2*>(Ch + o) = ph;
                        *reinterpret_cast<__half2*>(Cl + o) = pl;
                    }
                }
            }
        } else {
            // transpose fp16 -> Vt
#pragma unroll
            for (int fm = 0; fm < 4; fm++) {
#pragma unroll
                for (int fn = 0; fn < 4; fn++) {
                    int col = bx + wn + fn * 8 + ecol;
#pragma unroll
                    for (int half = 0; half < 2; half++) {
                        int row = by + wm + fm * 16 + erow + half * 8;
#pragma unroll
                        for (int e = 0; e < 2; e++) {
                            float vv = acc[fm][fn][half * 2 + e];
                            Vt16[(size_t)(col + e) * S + row] = __float2half_rn(vv);
                        }
                    }
                }
            }
        }
    }
}

// ---------------- fp16 1-term GEMM: O projection, dynamic scheduler ----------------
#define G16STAGE 16384u
#define NT_O ((D / 128) * (S / 128))   // 512

__global__ __launch_bounds__(256, 2) void gemmo_kernel(
    const __half* __restrict__ A16, const __half* __restrict__ B16,
    float* __restrict__ Cf)
{
    extern __shared__ char dsm[];
    const uint32_t smem = s2u(dsm);
    __shared__ int s_tile;

    const int tid = threadIdx.x;
    const int wid = tid >> 5;
    const int lane = tid & 31;
    const int wm = (wid & 1) * 64;
    const int wn = (wid >> 1) * 32;
    const int grp = lane >> 3;
    const int ri = lane & 7;

    while (true) {
        __syncthreads();
        if (tid == 0) s_tile = atomicAdd(&g_ctr2, 1);
        __syncthreads();
        const int tile = s_tile;
        if (tile >= NT_O) break;

        const int bx = (tile & 31) * 128;
        const int by = (tile >> 5) * 128;

        float acc[4][4][4];
#pragma unroll
        for (int i = 0; i < 4; i++)
#pragma unroll
            for (int j = 0; j < 4; j++)
#pragma unroll
                for (int e = 0; e < 4; e++) acc[i][j][e] = 0.0f;

        auto load_stage = [&](int c, int stage) {
            const uint32_t sb = smem + stage * G16STAGE;
            const int k0 = c << 5;
#pragma unroll
            for (int i = 0; i < 2; i++) {
                int idx = tid + i * 256;
                int row = idx >> 2, cc = idx & 3;
                uint32_t sc = (uint32_t)(cc ^ ((row >> 1) & 3));
                uint32_t so = (uint32_t)row * 64u + sc * 16u;
                cpasync16(sb + so,         A16 + (size_t)(by + row) * D + k0 + cc * 8);
                cpasync16(sb + GTILE + so, B16 + (size_t)(bx + row) * D + k0 + cc * 8);
            }
        };

        load_stage(0, 0);
        asm volatile("cp.async.commit_group;");
        load_stage(1, 1);
        asm volatile("cp.async.commit_group;");

        const int nchunks = D >> 5;
        for (int c = 0; c < nchunks; c++) {
            if (c + 1 < nchunks) asm volatile("cp.async.wait_group 1;");
            else                 asm volatile("cp.async.wait_group 0;");
            __syncthreads();
            if (c + 2 < nchunks) {
                load_stage(c + 2, (c + 2) % 3);
                asm volatile("cp.async.commit_group;");
            }
            const uint32_t sb = smem + (c % 3) * G16STAGE;
#pragma unroll
            for (int k16 = 0; k16 < 2; k16++) {
                const int lchunk = k16 * 2 + (grp >> 1);
                uint32_t ah[4][4];
#pragma unroll
                for (int fm = 0; fm < 4; fm++) {
                    int row = wm + fm * 16 + (grp & 1) * 8 + ri;
                    uint32_t ad = sb + (uint32_t)row * 64u
                                + (uint32_t)((lchunk ^ ((row >> 1) & 3)) * 16);
                    ldmx4(ah[fm], ad);
                }
#pragma unroll
                for (int fnp = 0; fnp < 2; fnp++) {
                    int row = wn + fnp * 16 + (grp & 1) * 8 + ri;
                    uint32_t bd = sb + GTILE + (uint32_t)row * 64u
                                + (uint32_t)((lchunk ^ ((row >> 1) & 3)) * 16);
                    uint32_t bh4[4];
                    ldmx4(bh4, bd);
                    uint32_t be[2] = {bh4[0], bh4[2]};
                    uint32_t bo[2] = {bh4[1], bh4[3]};
#pragma unroll
                    for (int fm = 0; fm < 4; fm++) {
                        mma16816h(acc[fm][2 * fnp],     ah[fm], be);
                        mma16816h(acc[fm][2 * fnp + 1], ah[fm], bo);
                    }
                }
            }
        }

        const int erow = lane >> 2;
        const int ecol = (lane & 3) * 2;
#pragma unroll
        for (int fm = 0; fm < 4; fm++) {
#pragma unroll
            for (int fn = 0; fn < 4; fn++) {
                float* cp0 = Cf + (size_t)(by + wm + fm * 16 + erow) * D + bx + wn + fn * 8 + ecol;
                float* cp1 = cp0 + 8 * (size_t)D;
                *reinterpret_cast<float2*>(cp0) = make_float2(acc[fm][fn][0], acc[fm][fn][1]);
                *reinterpret_cast<float2*>(cp1) = make_float2(acc[fm][fn][2], acc[fm][fn][3]);
            }
        }
    }
}

// ---------------- flash attention: all-fp16, Q overlaid on K smem (R12 version) ----------------
#define KPAD 272u
#define VPAD 144u
#define SM_KH 0u
#define SM_KL 17408u
#define SM_V  34816u
#define SM_TOT 53248u

__global__ __launch_bounds__(128, 3) void fattn_kernel(
    const __half* __restrict__ Qh, const __half* __restrict__ Ql,
    const __half* __restrict__ Kh, const __half* __restrict__ Kl,
    const __half* __restrict__ Vt16, __half* __restrict__ O16)
{
    extern __shared__ char dsm[];
    const uint32_t smem = s2u(dsm);
    const int tid = threadIdx.x;
    const int wid = tid >> 5, lane = tid & 31;
    const int qt = gridDim.x - 1 - blockIdx.x;
    const int h = blockIdx.y;
    const int kvh = h / NREP;
    const int q0 = qt * 64;

    const int r = lane >> 2;
    const int cgrp = lane & 3;
    const int grp = lane >> 3;
    const int ri = lane & 7;

    auto loadK = [&](int t) {
#pragma unroll
        for (int i = 0; i < 8; i++) {
            int idx = tid + i * 128;
            int row = idx >> 4, cc = idx & 15;
            size_t g = (size_t)(t * 64 + row) * KVD + kvh * HD + cc * 8;
            cpasync16(smem + SM_KH + row * KPAD + cc * 16, Kh + g);
            cpasync16(smem + SM_KL + row * KPAD + cc * 16, Kl + g);
        }
    };
    auto loadV = [&](int t) {
#pragma unroll
        for (int i = 0; i < 8; i++) {
            int idx = tid + i * 128;
            int row = idx >> 3, cc = idx & 7;
            size_t g = (size_t)(kvh * HD + row) * S + t * 64 + cc * 8;
            cpasync16(smem + SM_V + row * VPAD + cc * 16, Vt16 + g);
        }
    };

    // ---- stage Q into the K region, read to registers, then release ----
#pragma unroll
    for (int i = 0; i < 8; i++) {
        int idx = tid + i * 128;
        int row = idx >> 4, cc = idx & 15;
        size_t g = (size_t)(q0 + row) * D + h * HD + cc * 8;
        cpasync16(smem + SM_KH + row * KPAD + cc * 16, Qh + g);
        cpasync16(smem + SM_KL + row * KPAD + cc * 16, Ql + g);
    }
    asm volatile("cp.async.commit_group;");
    asm volatile("cp.async.wait_group 0;");
    __syncthreads();

    uint32_t qh[8][4], ql[8][4];
    {
        int qrow = wid * 16 + (grp & 1) * 8 + ri;
        uint32_t qbase = smem + SM_KH + (uint32_t)qrow * KPAD + (grp >> 1) * 16u;
#pragma unroll
        for (int ks = 0; ks < 8; ks++) {
            ldmx4(qh[ks], qbase + ks * 32u);
            ldmx4(ql[ks], qbase + ks * 32u + (SM_KL - SM_KH));
        }
    }
    __syncthreads();   // all warps done reading Q before K overwrites

    loadK(0);
    asm volatile("cp.async.commit_group;");

    float m0 = -1e30f, m1 = -1e30f, l0 = 0.0f, l1 = 0.0f;
    float oacc[16][4];
#pragma unroll
    for (int f = 0; f < 16; f++)
#pragma unroll
        for (int e = 0; e < 4; e++) oacc[f][e] = 0.0f;

    const int rowA = wid * 16 + r;
    const int rowB = rowA + 8;

    for (int t = 0; t <= qt; t++) {
        asm volatile("cp.async.wait_group 0;");
        __syncthreads();
        loadV(t);
        asm volatile("cp.async.commit_group;");

        float sacc[8][4];
#pragma unroll
        for (int f = 0; f < 8; f++)
#pragma unroll
            for (int e = 0; e < 4; e++) sacc[f][e] = 0.0f;

#pragma unroll
        for (int ks = 0; ks < 8; ks++) {
#pragma unroll
            for (int fnp = 0; fnp < 4; fnp++) {
                int krow = fnp * 16 + (grp & 1) * 8 + ri;
                uint32_t ka = smem + SM_KH + (uint32_t)krow * KPAD + ks * 32u + (grp >> 1) * 16u;
                uint32_t bh4[4], bl4[4];
                ldmx4(bh4, ka);
                ldmx4(bl4, ka + (SM_KL - SM_KH));
                uint32_t be[2]  = {bh4[0], bh4[2]};
                uint32_t bo[2]  = {bh4[1], bh4[3]};
                uint32_t ble[2] = {bl4[0], bl4[2]};
                uint32_t blo[2] = {bl4[1], bl4[3]};
                mma16816h(sacc[2 * fnp],     qh[ks], be);
                mma16816h(sacc[2 * fnp],     ql[ks], be);
                mma16816h(sacc[2 * fnp],     qh[ks], ble);
                mma16816h(sacc[2 * fnp + 1], qh[ks], bo);
                mma16816h(sacc[2 * fnp + 1], ql[ks], bo);
                mma16816h(sacc[2 * fnp + 1], qh[ks], blo);
            }
        }

        if (t == qt) {
#pragma unroll
            for (int fn = 0; fn < 8; fn++) {
                int c0 = fn * 8 + cgrp * 2;
                if (c0 > rowA) sacc[fn][0] = -1e30f;
                if (c0 + 1 > rowA) sacc[fn][1] = -1e30f;
                if (c0 > rowB) sacc[fn][2] = -1e30f;
                if (c0 + 1 > rowB) sacc[fn][3] = -1e30f;
            }
        }

        float tm0 = -1e30f, tm1 = -1e30f;
#pragma unroll
        for (int fn = 0; fn < 8; fn++) {
            tm0 = fmaxf(tm0, fmaxf(sacc[fn][0], sacc[fn][1]));
            tm1 = fmaxf(tm1, fmaxf(sacc[fn][2], sacc[fn][3]));
        }
        tm0 = fmaxf(tm0, __shfl_xor_sync(0xFFFFFFFFu, tm0, 1));
        tm0 = fmaxf(tm0, __shfl_xor_sync(0xFFFFFFFFu, tm0, 2));
        tm1 = fmaxf(tm1, __shfl_xor_sync(0xFFFFFFFFu, tm1, 1));
        tm1 = fmaxf(tm1, __shfl_xor_sync(0xFFFFFFFFu, tm1, 2));

        float mn0 = fmaxf(m0, tm0), mn1 = fmaxf(m1, tm1);
        float corr0 = exp2f(m0 - mn0), corr1 = exp2f(m1 - mn1);
        m0 = mn0; m1 = mn1;

        float rs0 = 0.0f, rs1 = 0.0f;
#pragma unroll
        for (int fn = 0; fn < 8; fn++) {
            sacc[fn][0] = exp2f(sacc[fn][0] - m0);
            sacc[fn][1] = exp2f(sacc[fn][1] - m0);
            sacc[fn][2] = exp2f(sacc[fn][2] - m1);
            sacc[fn][3] = exp2f(sacc[fn][3] - m1);
            rs0 += sacc[fn][0] + sacc[fn][1];
            rs1 += sacc[fn][2] + sacc[fn][3];
        }
        rs0 += __shfl_xor_sync(0xFFFFFFFFu, rs0, 1);
        rs0 += __shfl_xor_sync(0xFFFFFFFFu, rs0, 2);
        rs1 += __shfl_xor_sync(0xFFFFFFFFu, rs1, 1);
        rs1 += __shfl_xor_sync(0xFFFFFFFFu, rs1, 2);
        l0 = l0 * corr0 + rs0;
        l1 = l1 * corr1 + rs1;

#pragma unroll
        for (int f = 0; f < 16; f++) {
            oacc[f][0] *= corr0; oacc[f][1] *= corr0;
            oacc[f][2] *= corr1; oacc[f][3] *= corr1;
        }

        asm volatile("cp.async.wait_group 0;");
        __syncthreads();
        if (t < qt) {
            loadK(t + 1);
            asm volatile("cp.async.commit_group;");
        }

        // ---- O += P V (P single fp16, V single fp16) ----
#pragma unroll
        for (int kk = 0; kk < 4; kk++) {
            uint32_t aph[4];
#pragma unroll
            for (int half = 0; half < 2; half++) {
                const float* sp = sacc[2 * kk + half];
                aph[half * 2 + 0] = pack_f16(sp[0], sp[1]);
                aph[half * 2 + 1] = pack_f16(sp[2], sp[3]);
            }
#pragma unroll
            for (int fnp = 0; fnp < 8; fnp++) {
                int vrow = fnp * 16 + (grp & 1) * 8 + ri;
                uint32_t va = smem + SM_V + (uint32_t)vrow * VPAD + kk * 32u + (grp >> 1) * 16u;
                uint32_t bh4[4];
                ldmx4(bh4, va);
                uint32_t be[2] = {bh4[0], bh4[2]};
                uint32_t bo[2] = {bh4[1], bh4[3]};
                mma16816h(oacc[2 * fnp],     aph, be);
                mma16816h(oacc[2 * fnp + 1], aph, bo);
            }
        }
    }

    float inv0 = 1.0f / l0, inv1 = 1.0f / l1;
    const size_t gr0 = (size_t)(q0 + rowA) * D + h * HD + cgrp * 2;
    const size_t gr1 = (size_t)(q0 + rowB) * D + h * HD + cgrp * 2;
#pragma unroll
    for (int fn = 0; fn < 16; fn++) {
        *reinterpret_cast<__half2*>(O16 + gr0 + fn * 8) =
            __floats2half2_rn(oacc[fn][0] * inv0, oacc[fn][1] * inv0);
        *reinterpret_cast<__half2*>(O16 + gr1 + fn * 8) =
            __floats2half2_rn(oacc[fn][2] * inv1, oacc[fn][3] * inv1);
    }
}

// ---------------- launch ----------------
extern "C" void kernel_launch(void* const* d_in, const int* in_sizes, int n_in,
                              void* d_out, int out_size)
{
    const float* x    = (const float*)d_in[0];
    const float* wq   = (const float*)d_in[1];
    const float* wk   = (const float*)d_in[2];
    const float* wv   = (const float*)d_in[3];
    const float* wo   = (const float*)d_in[4];
    const float* cosb = (const float*)d_in[5];
    const float* sinb = (const float*)d_in[6];
    float* out = (float*)d_out;

    __half *x16h, *x16l, *a16, *q16h, *q16l, *k16h, *k16l, *vt16;
    __half *wq16, *wk16, *wv16, *wo16;
    cudaGetSymbolAddress((void**)&x16h, g_x16h); cudaGetSymbolAddress((void**)&x16l, g_x16l);
    cudaGetSymbolAddress((void**)&a16, g_a16);
    cudaGetSymbolAddress((void**)&q16h, g_q16h); cudaGetSymbolAddress((void**)&q16l, g_q16l);
    cudaGetSymbolAddress((void**)&k16h, g_k16h); cudaGetSymbolAddress((void**)&k16l, g_k16l);
    cudaGetSymbolAddress((void**)&vt16, g_vt16);
    cudaGetSymbolAddress((void**)&wq16, g_wq16); cudaGetSymbolAddress((void**)&wk16, g_wk16);
    cudaGetSymbolAddress((void**)&wv16, g_wv16); cudaGetSymbolAddress((void**)&wo16, g_wo16);

    const int shmem = 3 * (int)GSTAGE;        // 73728
    const int shmemo = 3 * (int)G16STAGE;     // 49152
    cudaFuncSetAttribute(proj_kernel, cudaFuncAttributeMaxDynamicSharedMemorySize, shmem);
    cudaFuncSetAttribute(gemmo_kernel, cudaFuncAttributeMaxDynamicSharedMemorySize, shmemo);
    cudaFuncSetAttribute(fattn_kernel, cudaFuncAttributeMaxDynamicSharedMemorySize, (int)SM_TOT);

    const float qscale = 0.08838834764831845f * 1.4426950408889634f;  // 1/sqrt(128)*log2(e)

    // input conversions
    xsplit16<<<(S * D / 4 + 255) / 256, 256>>>(x, x16h, x16l, S * D / 4);
    tsplit16_kernel<<<dim3(D / 32, D / 64), dim3(32, 8)>>>(wq, wq16, D, D);
    tsplit16_kernel<<<dim3(KVD / 32, D / 64), dim3(32, 8)>>>(wk, wk16, D, KVD);
    tsplit16_kernel<<<dim3(KVD / 32, D / 64), dim3(32, 8)>>>(wv, wv16, D, KVD);
    tsplit16_kernel<<<dim3(D / 32, D / 64), dim3(32, 8)>>>(wo, wo16, D, D);

    // unified Q/K/V projection, dynamic tile scheduler
    reset_ctr<<<1, 1>>>();
    proj_kernel<<<PGRID, 256, shmem>>>(
        x16h, x16l, wq16, wk16, wv16,
        q16h, q16l, k16h, k16l, vt16, cosb, sinb, qscale);

    // flash attention (log2-domain softmax, all fp16) -> fp16
    fattn_kernel<<<dim3(S / 64, H), 128, SM_TOT>>>(q16h, q16l, k16h, k16l, vt16, a16);

    // output projection: fp16 1-term, fp32 out, dynamic scheduler
    gemmo_kernel<<<PGRID, 256, shmemo>>>(a16, wo16, out);
}

// round 15
// speedup vs baseline: 1.0638x; 1.0638x over previous
#include <cuda_runtime.h>
#include <cuda_bf16.h>
#include <cuda_fp16.h>
#include <cstdint>

#define S 2048
#define D 4096
#define H 32
#define KVH 8
#define HD 128
#define NREP (H / KVH)
#define KVD (KVH * HD)
#define PGRID 304

// ---------------- scratch (static device arrays; no allocation) ----------------
__device__ __half g_x16h[S * D], g_x16l[S * D];
__device__ __half g_a16[S * D];
__device__ __half g_q16h[S * D], g_q16l[S * D];
__device__ __half g_k16h[S * KVD], g_k16l[S * KVD];
__device__ __half g_vt16[KVD * S];                 // transposed [KVD][S]
__device__ __half g_wq16[D * D];                   // transposed [N,K]
__device__ __half g_wk16[KVD * D];
__device__ __half g_wv16[KVD * D];
__device__ __half g_wo16[D * D];
__device__ int    g_ctr;

// ---------------- helpers ----------------
__device__ __forceinline__ uint32_t s2u(const void* p) {
    uint32_t a;
    asm("{ .reg .u64 t; cvta.to.shared.u64 t, %1; cvt.u32.u64 %0, t; }" : "=r"(a) : "l"(p));
    return a;
}
__device__ __forceinline__ void cpasync16(uint32_t saddr, const void* gaddr) {
    asm volatile("cp.async.cg.shared.global [%0], [%1], 16;" :: "r"(saddr), "l"(gaddr));
}
__device__ __forceinline__ void ldmx4(uint32_t* r, uint32_t addr) {
    asm volatile("ldmatrix.sync.aligned.m8n8.x4.shared.b16 {%0,%1,%2,%3}, [%4];"
                 : "=r"(r[0]), "=r"(r[1]), "=r"(r[2]), "=r"(r[3]) : "r"(addr));
}
__device__ __forceinline__ void mma16816h(float* d, const uint32_t* a, const uint32_t* b) {
    asm volatile(
        "mma.sync.aligned.m16n8k16.row.col.f32.f16.f16.f32 "
        "{%0,%1,%2,%3}, {%4,%5,%6,%7}, {%8,%9}, {%0,%1,%2,%3};"
        : "+f"(d[0]), "+f"(d[1]), "+f"(d[2]), "+f"(d[3])
        : "r"(a[0]), "r"(a[1]), "r"(a[2]), "r"(a[3]), "r"(b[0]), "r"(b[1]));
}
__device__ __forceinline__ uint32_t pack_f16(float x, float y) {
    __half2 t = __floats2half2_rn(x, y);
    return *reinterpret_cast<uint32_t*>(&t);
}
__device__ __forceinline__ void split2h(float v0, float v1, __half2& ph, __half2& pl) {
    __half h0 = __float2half_rn(v0), h1 = __float2half_rn(v1);
    ph = __halves2half2(h0, h1);
    pl = __halves2half2(__float2half_rn(v0 - __half2float(h0)),
                        __float2half_rn(v1 - __half2float(h1)));
}

// ---------------- counter reset ----------------
__global__ void reset_ctr() { g_ctr = 0; }

// ---------------- x: fp32 -> fp16 hi/lo ----------------
__global__ void xsplit16(const float* __restrict__ in,
                         __half* __restrict__ fh, __half* __restrict__ fl, int n4)
{
    int i = blockIdx.x * blockDim.x + threadIdx.x;
    if (i >= n4) return;
    float4 v = reinterpret_cast<const float4*>(in)[i];
    __half2 hh, hl;
    split2h(v.x, v.y, hh, hl);
    reinterpret_cast<__half2*>(fh)[2 * i] = hh;
    reinterpret_cast<__half2*>(fl)[2 * i] = hl;
    split2h(v.z, v.w, hh, hl);
    reinterpret_cast<__half2*>(fh)[2 * i + 1] = hh;
    reinterpret_cast<__half2*>(fl)[2 * i + 1] = hl;
}

// ---------------- transpose: W[K,N] fp32 -> fp16 [N,K], half2 writes ----------------
__global__ void tsplit16_kernel(const float* __restrict__ w,
                                __half* __restrict__ out, int K, int N)
{
    __shared__ float t[64][33];
    int n0 = blockIdx.x * 32, k0 = blockIdx.y * 64;
    int tx = threadIdx.x, ty = threadIdx.y;   // (32, 8)
    for (int r = ty; r < 64; r += 8)
        t[r][tx] = w[(size_t)(k0 + r) * N + n0 + tx];
    __syncthreads();
    for (int nn = ty; nn < 32; nn += 8) {
        __half2 h = __floats2half2_rn(t[2 * tx][nn], t[2 * tx + 1][nn]);
        *reinterpret_cast<__half2*>(out + (size_t)(n0 + nn) * K + k0 + 2 * tx) = h;
    }
}

#define GTILE  8192u
#define GSTAGE 24576u   // 3 tiles: A-hi, A-lo, B

// tile map: [0,128) K tiles, [128,640) Q tiles, [640,768) V tiles (1-term, light)
#define NT_K 128
#define NT_Q 512
#define NT_TOT 768

// ---------------- unified persistent projection kernel (all fp16) ----------------
__global__ __launch_bounds__(256, 2) void proj_kernel(
    const __half* __restrict__ X16h, const __half* __restrict__ X16l,
    const __half* __restrict__ Wq16, const __half* __restrict__ Wk16,
    const __half* __restrict__ Wv16,
    __half* __restrict__ Q16h, __half* __restrict__ Q16l,
    __half* __restrict__ K16h, __half* __restrict__ K16l,
    __half* __restrict__ Vt16,
    const float* __restrict__ cosb, const float* __restrict__ sinb, float qscale)
{
    extern __shared__ char dsm[];
    const uint32_t smem = s2u(dsm);
    __shared__ int s_tile;

    const int tid = threadIdx.x;
    const int wid = tid >> 5;
    const int lane = tid & 31;
    const int wm = (wid & 1) * 64;
    const int wn = (wid >> 1) * 32;
    const int grp = lane >> 3;
    const int ri = lane & 7;
    const int erow = lane >> 2;
    const int ecol = (lane & 3) * 2;
    const int nchunks = D >> 5;

    while (true) {
        __syncthreads();
        if (tid == 0) s_tile = atomicAdd(&g_ctr, 1);
        __syncthreads();
        const int t = s_tile;
        if (t >= NT_TOT) break;

        const bool isV = (t >= NT_K + NT_Q);
        const __half* B;
        __half *Ch = nullptr, *Cl = nullptr;
        int bx, by, Ndim = 0;
        float scale = 1.0f;
        if (t < NT_K) {
            B = Wk16; bx = (t & 7) * 128; by = (t >> 3) * 128;
            Ndim = KVD; Ch = K16h; Cl = K16l;
        } else if (!isV) {
            int q = t - NT_K;
            B = Wq16; bx = (q & 31) * 128; by = (q >> 5) * 128;
            Ndim = D; scale = qscale; Ch = Q16h; Cl = Q16l;
        } else {
            int v = t - NT_K - NT_Q;
            B = Wv16; bx = (v & 7) * 128; by = (v >> 3) * 128;
        }
        const bool two_term = !isV;

        float acc[4][4][4];
#pragma unroll
        for (int i = 0; i < 4; i++)
#pragma unroll
            for (int j = 0; j < 4; j++)
#pragma unroll
                for (int e = 0; e < 4; e++) acc[i][j][e] = 0.0f;

        auto load_stage = [&](int c, int stage) {
            const uint32_t sb = smem + stage * GSTAGE;
            const int k0 = c << 5;
#pragma unroll
            for (int i = 0; i < 2; i++) {
                int idx = tid + i * 256;
                int row = idx >> 2, cc = idx & 3;
                uint32_t sc = (uint32_t)(cc ^ ((row >> 1) & 3));
                uint32_t so = (uint32_t)row * 64u + sc * 16u;
                size_t ga = (size_t)(by + row) * D + k0 + cc * 8;
                cpasync16(sb + so, X16h + ga);
                if (two_term) cpasync16(sb + GTILE + so, X16l + ga);
                cpasync16(sb + 2 * GTILE + so, B + (size_t)(bx + row) * D + k0 + cc * 8);
            }
        };

        load_stage(0, 0);
        asm volatile("cp.async.commit_group;");
        load_stage(1, 1);
        asm volatile("cp.async.commit_group;");

        for (int c = 0; c < nchunks; c++) {
            if (c + 1 < nchunks) asm volatile("cp.async.wait_group 1;");
            else                 asm volatile("cp.async.wait_group 0;");
            __syncthreads();
            if (c + 2 < nchunks) {
                load_stage(c + 2, (c + 2) % 3);
                asm volatile("cp.async.commit_group;");
            }
            const uint32_t sb = smem + (c % 3) * GSTAGE;

#pragma unroll
            for (int k16 = 0; k16 < 2; k16++) {
                const int lchunk = k16 * 2 + (grp >> 1);
                uint32_t ah[4][4], al[4][4];
#pragma unroll
                for (int fm = 0; fm < 4; fm++) {
                    int row = wm + fm * 16 + (grp & 1) * 8 + ri;
                    uint32_t ad = sb + (uint32_t)row * 64u
                                + (uint32_t)((lchunk ^ ((row >> 1) & 3)) * 16);
                    ldmx4(ah[fm], ad);
                    if (two_term) ldmx4(al[fm], ad + GTILE);
                }
#pragma unroll
                for (int fnp = 0; fnp < 2; fnp++) {
                    int row = wn + fnp * 16 + (grp & 1) * 8 + ri;
                    uint32_t bd = sb + 2 * GTILE + (uint32_t)row * 64u
                                + (uint32_t)((lchunk ^ ((row >> 1) & 3)) * 16);
                    uint32_t bh4[4];
                    ldmx4(bh4, bd);
                    uint32_t be[2] = {bh4[0], bh4[2]};
                    uint32_t bo[2] = {bh4[1], bh4[3]};
#pragma unroll
                    for (int fm = 0; fm < 4; fm++) {
                        mma16816h(acc[fm][2 * fnp],     ah[fm], be);
                        mma16816h(acc[fm][2 * fnp + 1], ah[fm], bo);
                        if (two_term) {
                            mma16816h(acc[fm][2 * fnp],     al[fm], be);
                            mma16816h(acc[fm][2 * fnp + 1], al[fm], bo);
                        }
                    }
                }
            }
        }

        if (!isV) {
            // RoPE + scale + fp16 split
#pragma unroll
            for (int fm = 0; fm < 4; fm++) {
#pragma unroll
                for (int fn = 0; fn < 4; fn++) {
                    int col = bx + wn + fn * 8 + ecol;
                    int i = (col & 127) >> 1;
#pragma unroll
                    for (int half = 0; half < 2; half++) {
                        int row = by + wm + fm * 16 + erow + half * 8;
                        float cv = cosb[row * 64 + i];
                        float sv = sinb[row * 64 + i];
                        float t0 = acc[fm][fn][half * 2], t1 = acc[fm][fn][half * 2 + 1];
                        float o0 = (t0 * cv - t1 * sv) * scale;
                        float o1 = (t0 * sv + t1 * cv) * scale;
                        __half2 ph, pl;
                        split2h(o0, o1, ph, pl);
                        size_t o = (size_t)row * Ndim + col;
                        *reinterpret_cast<__half2*>(Ch + o) = ph;
                        *reinterpret_cast<__half2*>(Cl + o) = pl;
                    }
                }
            }
        } else {
            // transpose fp16 -> Vt
#pragma unroll
            for (int fm = 0; fm < 4; fm++) {
#pragma unroll
                for (int fn = 0; fn < 4; fn++) {
                    int col = bx + wn + fn * 8 + ecol;
#pragma unroll
                    for (int half = 0; half < 2; half++) {
                        int row = by + wm + fm * 16 + erow + half * 8;
#pragma unroll
                        for (int e = 0; e < 2; e++) {
                            float vv = acc[fm][fn][half * 2 + e];
                            Vt16[(size_t)(col + e) * S + row] = __float2half_rn(vv);
                        }
                    }
                }
            }
        }
    }
}

// ---------------- fp16 1-term GEMM: O projection, static persistent ----------------
#define G16STAGE 16384u

__global__ __launch_bounds__(256, 2) void gemmo_kernel(
    const __half* __restrict__ A16, const __half* __restrict__ B16,
    float* __restrict__ Cf, int Ndim, int Kdim, int ntx, int ntiles)
{
    extern __shared__ char dsm[];
    const uint32_t smem = s2u(dsm);

    const int tid = threadIdx.x;
    const int wid = tid >> 5;
    const int lane = tid & 31;
    const int wm = (wid & 1) * 64;
    const int wn = (wid >> 1) * 32;
    const int grp = lane >> 3;
    const int ri = lane & 7;

    for (int tile = blockIdx.x; tile < ntiles; tile += gridDim.x) {
        const int bx = (tile % ntx) * 128;
        const int by = (tile / ntx) * 128;

        float acc[4][4][4];
#pragma unroll
        for (int i = 0; i < 4; i++)
#pragma unroll
            for (int j = 0; j < 4; j++)
#pragma unroll
                for (int e = 0; e < 4; e++) acc[i][j][e] = 0.0f;

        auto load_stage = [&](int c, int stage) {
            const uint32_t sb = smem + stage * G16STAGE;
            const int k0 = c << 5;
#pragma unroll
            for (int i = 0; i < 2; i++) {
                int idx = tid + i * 256;
                int row = idx >> 2, cc = idx & 3;
                uint32_t sc = (uint32_t)(cc ^ ((row >> 1) & 3));
                uint32_t so = (uint32_t)row * 64u + sc * 16u;
                cpasync16(sb + so,         A16 + (size_t)(by + row) * Kdim + k0 + cc * 8);
                cpasync16(sb + GTILE + so, B16 + (size_t)(bx + row) * Kdim + k0 + cc * 8);
            }
        };

        load_stage(0, 0);
        asm volatile("cp.async.commit_group;");
        load_stage(1, 1);
        asm volatile("cp.async.commit_group;");

        const int nchunks = Kdim >> 5;
        for (int c = 0; c < nchunks; c++) {
            if (c + 1 < nchunks) asm volatile("cp.async.wait_group 1;");
            else                 asm volatile("cp.async.wait_group 0;");
            __syncthreads();
            if (c + 2 < nchunks) {
                load_stage(c + 2, (c + 2) % 3);
                asm volatile("cp.async.commit_group;");
            }
            const uint32_t sb = smem + (c % 3) * G16STAGE;
#pragma unroll
            for (int k16 = 0; k16 < 2; k16++) {
                const int lchunk = k16 * 2 + (grp >> 1);
                uint32_t ah[4][4];
#pragma unroll
                for (int fm = 0; fm < 4; fm++) {
                    int row = wm + fm * 16 + (grp & 1) * 8 + ri;
                    uint32_t ad = sb + (uint32_t)row * 64u
                                + (uint32_t)((lchunk ^ ((row >> 1) & 3)) * 16);
                    ldmx4(ah[fm], ad);
                }
#pragma unroll
                for (int fnp = 0; fnp < 2; fnp++) {
                    int row = wn + fnp * 16 + (grp & 1) * 8 + ri;
                    uint32_t bd = sb + GTILE + (uint32_t)row * 64u
                                + (uint32_t)((lchunk ^ ((row >> 1) & 3)) * 16);
                    uint32_t bh4[4];
                    ldmx4(bh4, bd);
                    uint32_t be[2] = {bh4[0], bh4[2]};
                    uint32_t bo[2] = {bh4[1], bh4[3]};
#pragma unroll
                    for (int fm = 0; fm < 4; fm++) {
                        mma16816h(acc[fm][2 * fnp],     ah[fm], be);
                        mma16816h(acc[fm][2 * fnp + 1], ah[fm], bo);
                    }
                }
            }
        }

        const int erow = lane >> 2;
        const int ecol = (lane & 3) * 2;
#pragma unroll
        for (int fm = 0; fm < 4; fm++) {
#pragma unroll
            for (int fn = 0; fn < 4; fn++) {
                float* cp0 = Cf + (size_t)(by + wm + fm * 16 + erow) * Ndim + bx + wn + fn * 8 + ecol;
                float* cp1 = cp0 + 8 * (size_t)Ndim;
                *reinterpret_cast<float2*>(cp0) = make_float2(acc[fm][fn][0], acc[fm][fn][1]);
                *reinterpret_cast<float2*>(cp1) = make_float2(acc[fm][fn][2], acc[fm][fn][3]);
            }
        }
        __syncthreads();
    }
}

// ---------------- flash attention: all-fp16, Q overlaid on K smem ----------------
#define KPAD 272u
#define VPAD 144u
#define SM_KH 0u
#define SM_KL 17408u
#define SM_V  34816u
#define SM_TOT 53248u

__global__ __launch_bounds__(128, 3) void fattn_kernel(
    const __half* __restrict__ Qh, const __half* __restrict__ Ql,
    const __half* __restrict__ Kh, const __half* __restrict__ Kl,
    const __half* __restrict__ Vt16, __half* __restrict__ O16)
{
    extern __shared__ char dsm[];
    const uint32_t smem = s2u(dsm);
    const int tid = threadIdx.x;
    const int wid = tid >> 5, lane = tid & 31;
    const int qt = gridDim.x - 1 - blockIdx.x;
    const int h = blockIdx.y;
    const int kvh = h / NREP;
    const int q0 = qt * 64;

    const int r = lane >> 2;
    const int cgrp = lane & 3;
    const int grp = lane >> 3;
    const int ri = lane & 7;

    auto loadK = [&](int t) {
#pragma unroll
        for (int i = 0; i < 8; i++) {
            int idx = tid + i * 128;
            int row = idx >> 4, cc = idx & 15;
            size_t g = (size_t)(t * 64 + row) * KVD + kvh * HD + cc * 8;
            cpasync16(smem + SM_KH + row * KPAD + cc * 16, Kh + g);
            cpasync16(smem + SM_KL + row * KPAD + cc * 16, Kl + g);
        }
    };
    auto loadV = [&](int t) {
#pragma unroll
        for (int i = 0; i < 8; i++) {
            int idx = tid + i * 128;
            int row = idx >> 3, cc = idx & 7;
            size_t g = (size_t)(kvh * HD + row) * S + t * 64 + cc * 8;
            cpasync16(smem + SM_V + row * VPAD + cc * 16, Vt16 + g);
        }
    };

    // ---- stage Q into the K region, read to registers, then release ----
#pragma unroll
    for (int i = 0; i < 8; i++) {
        int idx = tid + i * 128;
        int row = idx >> 4, cc = idx & 15;
        size_t g = (size_t)(q0 + row) * D + h * HD + cc * 8;
        cpasync16(smem + SM_KH + row * KPAD + cc * 16, Qh + g);
        cpasync16(smem + SM_KL + row * KPAD + cc * 16, Ql + g);
    }
    asm volatile("cp.async.commit_group;");
    asm volatile("cp.async.wait_group 0;");
    __syncthreads();

    uint32_t qh[8][4], ql[8][4];
    {
        int qrow = wid * 16 + (grp & 1) * 8 + ri;
        uint32_t qbase = smem + SM_KH + (uint32_t)qrow * KPAD + (grp >> 1) * 16u;
#pragma unroll
        for (int ks = 0; ks < 8; ks++) {
            ldmx4(qh[ks], qbase + ks * 32u);
            ldmx4(ql[ks], qbase + ks * 32u + (SM_KL - SM_KH));
        }
    }
    __syncthreads();   // all warps done reading Q before K overwrites

    loadK(0);
    asm volatile("cp.async.commit_group;");

    float m0 = -1e30f, m1 = -1e30f, l0 = 0.0f, l1 = 0.0f;
    float oacc[16][4];
#pragma unroll
    for (int f = 0; f < 16; f++)
#pragma unroll
        for (int e = 0; e < 4; e++) oacc[f][e] = 0.0f;

    const int rowA = wid * 16 + r;
    const int rowB = rowA + 8;

    for (int t = 0; t <= qt; t++) {
        asm volatile("cp.async.wait_group 0;");
        __syncthreads();
        loadV(t);
        asm volatile("cp.async.commit_group;");

        float sacc[8][4];
#pragma unroll
        for (int f = 0; f < 8; f++)
#pragma unroll
            for (int e = 0; e < 4; e++) sacc[f][e] = 0.0f;

#pragma unroll
        for (int ks = 0; ks < 8; ks++) {
#pragma unroll
            for (int fnp = 0; fnp < 4; fnp++) {
                int krow = fnp * 16 + (grp & 1) * 8 + ri;
                uint32_t ka = smem + SM_KH + (uint32_t)krow * KPAD + ks * 32u + (grp >> 1) * 16u;
                uint32_t bh4[4], bl4[4];
                ldmx4(bh4, ka);
                ldmx4(bl4, ka + (SM_KL - SM_KH));
                uint32_t be[2]  = {bh4[0], bh4[2]};
                uint32_t bo[2]  = {bh4[1], bh4[3]};
                uint32_t ble[2] = {bl4[0], bl4[2]};
                uint32_t blo[2] = {bl4[1], bl4[3]};
                mma16816h(sacc[2 * fnp],     qh[ks], be);
                mma16816h(sacc[2 * fnp],     ql[ks], be);
                mma16816h(sacc[2 * fnp],     qh[ks], ble);
                mma16816h(sacc[2 * fnp + 1], qh[ks], bo);
                mma16816h(sacc[2 * fnp + 1], ql[ks], bo);
                mma16816h(sacc[2 * fnp + 1], qh[ks], blo);
            }
        }

        if (t == qt) {
#pragma unroll
            for (int fn = 0; fn < 8; fn++) {
                int c0 = fn * 8 + cgrp * 2;
                if (c0 > rowA) sacc[fn][0] = -1e30f;
                if (c0 + 1 > rowA) sacc[fn][1] = -1e30f;
                if (c0 > rowB) sacc[fn][2] = -1e30f;
                if (c0 + 1 > rowB) sacc[fn][3] = -1e30f;
            }
        }

        float tm0 = -1e30f, tm1 = -1e30f;
#pragma unroll
        for (int fn = 0; fn < 8; fn++) {
            tm0 = fmaxf(tm0, fmaxf(sacc[fn][0], sacc[fn][1]));
            tm1 = fmaxf(tm1, fmaxf(sacc[fn][2], sacc[fn][3]));
        }
        tm0 = fmaxf(tm0, __shfl_xor_sync(0xFFFFFFFFu, tm0, 1));
        tm0 = fmaxf(tm0, __shfl_xor_sync(0xFFFFFFFFu, tm0, 2));
        tm1 = fmaxf(tm1, __shfl_xor_sync(0xFFFFFFFFu, tm1, 1));
        tm1 = fmaxf(tm1, __shfl_xor_sync(0xFFFFFFFFu, tm1, 2));

        float mn0 = fmaxf(m0, tm0), mn1 = fmaxf(m1, tm1);
        float corr0 = exp2f(m0 - mn0), corr1 = exp2f(m1 - mn1);
        m0 = mn0; m1 = mn1;

        float rs0 = 0.0f, rs1 = 0.0f;
#pragma unroll
        for (int fn = 0; fn < 8; fn++) {
            sacc[fn][0] = exp2f(sacc[fn][0] - m0);
            sacc[fn][1] = exp2f(sacc[fn][1] - m0);
            sacc[fn][2] = exp2f(sacc[fn][2] - m1);
            sacc[fn][3] = exp2f(sacc[fn][3] - m1);
            rs0 += sacc[fn][0] + sacc[fn][1];
            rs1 += sacc[fn][2] + sacc[fn][3];
        }
        rs0 += __shfl_xor_sync(0xFFFFFFFFu, rs0, 1);
        rs0 += __shfl_xor_sync(0xFFFFFFFFu, rs0, 2);
        rs1 += __shfl_xor_sync(0xFFFFFFFFu, rs1, 1);
        rs1 += __shfl_xor_sync(0xFFFFFFFFu, rs1, 2);
        l0 = l0 * corr0 + rs0;
        l1 = l1 * corr1 + rs1;

#pragma unroll
        for (int f = 0; f < 16; f++) {
            oacc[f][0] *= corr0; oacc[f][1] *= corr0;
            oacc[f][2] *= corr1; oacc[f][3] *= corr1;
        }

        asm volatile("cp.async.wait_group 0;");
        __syncthreads();
        if (t < qt) {
            loadK(t + 1);
            asm volatile("cp.async.commit_group;");
        }

        // ---- O += P V (P single fp16, V single fp16) ----
#pragma unroll
        for (int kk = 0; kk < 4; kk++) {
            uint32_t aph[4];
#pragma unroll
            for (int half = 0; half < 2; half++) {
                const float* sp = sacc[2 * kk + half];
                aph[half * 2 + 0] = pack_f16(sp[0], sp[1]);
                aph[half * 2 + 1] = pack_f16(sp[2], sp[3]);
            }
#pragma unroll
            for (int fnp = 0; fnp < 8; fnp++) {
                int vrow = fnp * 16 + (grp & 1) * 8 + ri;
                uint32_t va = smem + SM_V + (uint32_t)vrow * VPAD + kk * 32u + (grp >> 1) * 16u;
                uint32_t bh4[4];
                ldmx4(bh4, va);
                uint32_t be[2] = {bh4[0], bh4[2]};
                uint32_t bo[2] = {bh4[1], bh4[3]};
                mma16816h(oacc[2 * fnp],     aph, be);
                mma16816h(oacc[2 * fnp + 1], aph, bo);
            }
        }
    }

    float inv0 = 1.0f / l0, inv1 = 1.0f / l1;
    const size_t gr0 = (size_t)(q0 + rowA) * D + h * HD + cgrp * 2;
    const size_t gr1 = (size_t)(q0 + rowB) * D + h * HD + cgrp * 2;
#pragma unroll
    for (int fn = 0; fn < 16; fn++) {
        *reinterpret_cast<__half2*>(O16 + gr0 + fn * 8) =
            __floats2half2_rn(oacc[fn][0] * inv0, oacc[fn][1] * inv0);
        *reinterpret_cast<__half2*>(O16 + gr1 + fn * 8) =
            __floats2half2_rn(oacc[fn][2] * inv1, oacc[fn][3] * inv1);
    }
}

// ---------------- launch ----------------
extern "C" void kernel_launch(void* const* d_in, const int* in_sizes, int n_in,
                              void* d_out, int out_size)
{
    const float* x    = (const float*)d_in[0];
    const float* wq   = (const float*)d_in[1];
    const float* wk   = (const float*)d_in[2];
    const float* wv   = (const float*)d_in[3];
    const float* wo   = (const float*)d_in[4];
    const float* cosb = (const float*)d_in[5];
    const float* sinb = (const float*)d_in[6];
    float* out = (float*)d_out;

    __half *x16h, *x16l, *a16, *q16h, *q16l, *k16h, *k16l, *vt16;
    __half *wq16, *wk16, *wv16, *wo16;
    cudaGetSymbolAddress((void**)&x16h, g_x16h); cudaGetSymbolAddress((void**)&x16l, g_x16l);
    cudaGetSymbolAddress((void**)&a16, g_a16);
    cudaGetSymbolAddress((void**)&q16h, g_q16h); cudaGetSymbolAddress((void**)&q16l, g_q16l);
    cudaGetSymbolAddress((void**)&k16h, g_k16h); cudaGetSymbolAddress((void**)&k16l, g_k16l);
    cudaGetSymbolAddress((void**)&vt16, g_vt16);
    cudaGetSymbolAddress((void**)&wq16, g_wq16); cudaGetSymbolAddress((void**)&wk16, g_wk16);
    cudaGetSymbolAddress((void**)&wv16, g_wv16); cudaGetSymbolAddress((void**)&wo16, g_wo16);

    const int shmem = 3 * (int)GSTAGE;        // 73728
    const int shmemo = 3 * (int)G16STAGE;     // 49152
    cudaFuncSetAttribute(proj_kernel, cudaFuncAttributeMaxDynamicSharedMemorySize, shmem);
    cudaFuncSetAttribute(gemmo_kernel, cudaFuncAttributeMaxDynamicSharedMemorySize, shmemo);
    cudaFuncSetAttribute(fattn_kernel, cudaFuncAttributeMaxDynamicSharedMemorySize, (int)SM_TOT);

    const float qscale = 0.08838834764831845f * 1.4426950408889634f;  // 1/sqrt(128)*log2(e)

    // input conversions
    xsplit16<<<(S * D / 4 + 255) / 256, 256>>>(x, x16h, x16l, S * D / 4);
    tsplit16_kernel<<<dim3(D / 32, D / 64), dim3(32, 8)>>>(wq, wq16, D, D);
    tsplit16_kernel<<<dim3(KVD / 32, D / 64), dim3(32, 8)>>>(wk, wk16, D, KVD);
    tsplit16_kernel<<<dim3(KVD / 32, D / 64), dim3(32, 8)>>>(wv, wv16, D, KVD);
    tsplit16_kernel<<<dim3(D / 32, D / 64), dim3(32, 8)>>>(wo, wo16, D, D);

    // unified Q/K/V projection, dynamic tile scheduler
    reset_ctr<<<1, 1>>>();
    proj_kernel<<<PGRID, 256, shmem>>>(
        x16h, x16l, wq16, wk16, wv16,
        q16h, q16l, k16h, k16l, vt16, cosb, sinb, qscale);

    // flash attention (log2-domain softmax, all fp16) -> fp16
    fattn_kernel<<<dim3(S / 64, H), 128, SM_TOT>>>(q16h, q16l, k16h, k16l, vt16, a16);

    // output projection: fp16 1-term, fp32 out, static persistent
    gemmo_kernel<<<PGRID, 256, shmemo>>>(
        a16, wo16, out, D, D, D / 128, (D / 128) * (S / 128));
}

// round 16
// speedup vs baseline: 1.1674x; 1.0974x over previous
#include <cuda_runtime.h>
#include <cuda_bf16.h>
#include <cuda_fp16.h>
#include <cstdint>

#define S 2048
#define D 4096
#define H 32
#define KVH 8
#define HD 128
#define NREP (H / KVH)
#define KVD (KVH * HD)
#define PGRID 304

// ---------------- scratch (static device arrays; no allocation) ----------------
__device__ __half g_x16h[S * D], g_x16l[S * D];
__device__ __half g_a16[S * D];
__device__ __half g_q16h[S * D], g_q16l[S * D];
__device__ __half g_k16h[S * KVD], g_k16l[S * KVD];
__device__ __half g_vt16[KVD * S];                 // transposed [KVD][S]
__device__ __half g_wq16[D * D];                   // native [K,N] fp16
__device__ __half g_wk16[D * KVD];
__device__ __half g_wv16[D * KVD];
__device__ __half g_wo16[D * D];
__device__ int    g_ctr;

// ---------------- helpers ----------------
__device__ __forceinline__ uint32_t s2u(const void* p) {
    uint32_t a;
    asm("{ .reg .u64 t; cvta.to.shared.u64 t, %1; cvt.u32.u64 %0, t; }" : "=r"(a) : "l"(p));
    return a;
}
__device__ __forceinline__ void cpasync16(uint32_t saddr, const void* gaddr) {
    asm volatile("cp.async.cg.shared.global [%0], [%1], 16;" :: "r"(saddr), "l"(gaddr));
}
__device__ __forceinline__ void ldmx4(uint32_t* r, uint32_t addr) {
    asm volatile("ldmatrix.sync.aligned.m8n8.x4.shared.b16 {%0,%1,%2,%3}, [%4];"
                 : "=r"(r[0]), "=r"(r[1]), "=r"(r[2]), "=r"(r[3]) : "r"(addr));
}
__device__ __forceinline__ void ldmx4t(uint32_t* r, uint32_t addr) {
    asm volatile("ldmatrix.sync.aligned.m8n8.x4.trans.shared.b16 {%0,%1,%2,%3}, [%4];"
                 : "=r"(r[0]), "=r"(r[1]), "=r"(r[2]), "=r"(r[3]) : "r"(addr));
}
__device__ __forceinline__ void mma16816h(float* d, const uint32_t* a, const uint32_t* b) {
    asm volatile(
        "mma.sync.aligned.m16n8k16.row.col.f32.f16.f16.f32 "
        "{%0,%1,%2,%3}, {%4,%5,%6,%7}, {%8,%9}, {%0,%1,%2,%3};"
        : "+f"(d[0]), "+f"(d[1]), "+f"(d[2]), "+f"(d[3])
        : "r"(a[0]), "r"(a[1]), "r"(a[2]), "r"(a[3]), "r"(b[0]), "r"(b[1]));
}
__device__ __forceinline__ uint32_t pack_f16(float x, float y) {
    __half2 t = __floats2half2_rn(x, y);
    return *reinterpret_cast<uint32_t*>(&t);
}
__device__ __forceinline__ void split2h(float v0, float v1, __half2& ph, __half2& pl) {
    __half h0 = __float2half_rn(v0), h1 = __float2half_rn(v1);
    ph = __halves2half2(h0, h1);
    pl = __halves2half2(__float2half_rn(v0 - __half2float(h0)),
                        __float2half_rn(v1 - __half2float(h1)));
}

// ---------------- counter reset ----------------
__global__ void reset_ctr() { g_ctr = 0; }

// ---------------- x: fp32 -> fp16 hi/lo ----------------
__global__ void xsplit16(const float* __restrict__ in,
                         __half* __restrict__ fh, __half* __restrict__ fl, int n4)
{
    int i = blockIdx.x * blockDim.x + threadIdx.x;
    if (i >= n4) return;
    float4 v = reinterpret_cast<const float4*>(in)[i];
    __half2 hh, hl;
    split2h(v.x, v.y, hh, hl);
    reinterpret_cast<__half2*>(fh)[2 * i] = hh;
    reinterpret_cast<__half2*>(fl)[2 * i] = hl;
    split2h(v.z, v.w, hh, hl);
    reinterpret_cast<__half2*>(fh)[2 * i + 1] = hh;
    reinterpret_cast<__half2*>(fl)[2 * i + 1] = hl;
}

// ---------------- streaming convert: fp32 -> fp16, same layout ----------------
__global__ void wconv16(const float* __restrict__ in, __half* __restrict__ out, int n4)
{
    int i = blockIdx.x * blockDim.x + threadIdx.x;
    if (i >= n4) return;
    float4 v = reinterpret_cast<const float4*>(in)[i];
    reinterpret_cast<__half2*>(out)[2 * i]     = __floats2half2_rn(v.x, v.y);
    reinterpret_cast<__half2*>(out)[2 * i + 1] = __floats2half2_rn(v.z, v.w);
}

#define GTILE  8192u
#define GSTAGE 24576u   // 3 tiles: A-hi, A-lo, B

// tile map: [0,128) K tiles, [128,640) Q tiles, [640,768) V tiles (1-term, light)
#define NT_K 128
#define NT_Q 512
#define NT_TOT 768

// ---------------- unified persistent projection kernel (all fp16) ----------------
__global__ __launch_bounds__(256, 2) void proj_kernel(
    const __half* __restrict__ X16h, const __half* __restrict__ X16l,
    const __half* __restrict__ Wq16, const __half* __restrict__ Wk16,
    const __half* __restrict__ Wv16,
    __half* __restrict__ Q16h, __half* __restrict__ Q16l,
    __half* __restrict__ K16h, __half* __restrict__ K16l,
    __half* __restrict__ Vt16,
    const float* __restrict__ cosb, const float* __restrict__ sinb, float qscale)
{
    extern __shared__ char dsm[];
    const uint32_t smem = s2u(dsm);
    __shared__ int s_tile;

    const int tid = threadIdx.x;
    const int wid = tid >> 5;
    const int lane = tid & 31;
    const int wm = (wid & 1) * 64;
    const int wn = (wid >> 1) * 32;
    const int grp = lane >> 3;
    const int ri = lane & 7;
    const int erow = lane >> 2;
    const int ecol = (lane & 3) * 2;
    const int nchunks = D >> 5;

    while (true) {
        __syncthreads();
        if (tid == 0) s_tile = atomicAdd(&g_ctr, 1);
        __syncthreads();
        const int t = s_tile;
        if (t >= NT_TOT) break;

        const bool isV = (t >= NT_K + NT_Q);
        const __half* B;
        __half *Ch = nullptr, *Cl = nullptr;
        int bx, by, Ndim = 0, Bn;
        float scale = 1.0f;
        if (t < NT_K) {
            B = Wk16; bx = (t & 7) * 128; by = (t >> 3) * 128;
            Ndim = KVD; Bn = KVD; Ch = K16h; Cl = K16l;
        } else if (!isV) {
            int q = t - NT_K;
            B = Wq16; bx = (q & 31) * 128; by = (q >> 5) * 128;
            Ndim = D; Bn = D; scale = qscale; Ch = Q16h; Cl = Q16l;
        } else {
            int v = t - NT_K - NT_Q;
            B = Wv16; bx = (v & 7) * 128; by = (v >> 3) * 128;
            Bn = KVD;
        }
        const bool two_term = !isV;

        float acc[4][4][4];
#pragma unroll
        for (int i = 0; i < 4; i++)
#pragma unroll
            for (int j = 0; j < 4; j++)
#pragma unroll
                for (int e = 0; e < 4; e++) acc[i][j][e] = 0.0f;

        auto load_stage = [&](int c, int stage) {
            const uint32_t sb = smem + stage * GSTAGE;
            const int k0 = c << 5;
#pragma unroll
            for (int i = 0; i < 2; i++) {
                int idx = tid + i * 256;
                // A: 128 rows x 64B, old swizzle
                int row = idx >> 2, cc = idx & 3;
                uint32_t sc = (uint32_t)(cc ^ ((row >> 1) & 3));
                uint32_t so = (uint32_t)row * 64u + sc * 16u;
                size_t ga = (size_t)(by + row) * D + k0 + cc * 8;
                cpasync16(sb + so, X16h + ga);
                if (two_term) cpasync16(sb + GTILE + so, X16l + ga);
                // B: [K,N] native, 32 rows(k) x 256B, 16B-unit XOR swizzle
                int brow = idx >> 4, bc = idx & 15;
                uint32_t bsc = (uint32_t)(bc ^ (brow & 15));
                cpasync16(sb + 2 * GTILE + (uint32_t)brow * 256u + bsc * 16u,
                          B + (size_t)(k0 + brow) * Bn + bx + bc * 8);
            }
        };

        load_stage(0, 0);
        asm volatile("cp.async.commit_group;");
        load_stage(1, 1);
        asm volatile("cp.async.commit_group;");

        for (int c = 0; c < nchunks; c++) {
            if (c + 1 < nchunks) asm volatile("cp.async.wait_group 1;");
            else                 asm volatile("cp.async.wait_group 0;");
            __syncthreads();
            if (c + 2 < nchunks) {
                load_stage(c + 2, (c + 2) % 3);
                asm volatile("cp.async.commit_group;");
            }
            const uint32_t sb = smem + (c % 3) * GSTAGE;

#pragma unroll
            for (int k16 = 0; k16 < 2; k16++) {
                const int lchunk = k16 * 2 + (grp >> 1);
                uint32_t ah[4][4], al[4][4];
#pragma unroll
                for (int fm = 0; fm < 4; fm++) {
                    int row = wm + fm * 16 + (grp & 1) * 8 + ri;
                    uint32_t ad = sb + (uint32_t)row * 64u
                                + (uint32_t)((lchunk ^ ((row >> 1) & 3)) * 16);
                    ldmx4(ah[fm], ad);
                    if (two_term) ldmx4(al[fm], ad + GTILE);
                }
                const int krow = (k16 * 16) + (lane & 15);  // local k row 0..31
#pragma unroll
                for (int fnp = 0; fnp < 2; fnp++) {
                    int ncol16 = ((wn + fnp * 16) >> 3) + (lane >> 4);
                    uint32_t bsc = (uint32_t)(ncol16 ^ (krow & 15));
                    uint32_t bd = sb + 2 * GTILE + (uint32_t)krow * 256u + bsc * 16u;
                    uint32_t bh4[4];
                    ldmx4t(bh4, bd);
                    uint32_t be[2] = {bh4[0], bh4[1]};
                    uint32_t bo[2] = {bh4[2], bh4[3]};
#pragma unroll
                    for (int fm = 0; fm < 4; fm++) {
                        mma16816h(acc[fm][2 * fnp],     ah[fm], be);
                        mma16816h(acc[fm][2 * fnp + 1], ah[fm], bo);
                        if (two_term) {
                            mma16816h(acc[fm][2 * fnp],     al[fm], be);
                            mma16816h(acc[fm][2 * fnp + 1], al[fm], bo);
                        }
                    }
                }
            }
        }

        if (!isV) {
            // RoPE + scale + fp16 split
#pragma unroll
            for (int fm = 0; fm < 4; fm++) {
#pragma unroll
                for (int fn = 0; fn < 4; fn++) {
                    int col = bx + wn + fn * 8 + ecol;
                    int i = (col & 127) >> 1;
#pragma unroll
                    for (int half = 0; half < 2; half++) {
                        int row = by + wm + fm * 16 + erow + half * 8;
                        float cv = cosb[row * 64 + i];
                        float sv = sinb[row * 64 + i];
                        float t0 = acc[fm][fn][half * 2], t1 = acc[fm][fn][half * 2 + 1];
                        float o0 = (t0 * cv - t1 * sv) * scale;
                        float o1 = (t0 * sv + t1 * cv) * scale;
                        __half2 ph, pl;
                        split2h(o0, o1, ph, pl);
                        size_t o = (size_t)row * Ndim + col;
                        *reinterpret_cast<__half2*>(Ch + o) = ph;
                        *reinterpret_cast<__half2*>(Cl + o) = pl;
                    }
                }
            }
        } else {
            // transpose fp16 -> Vt
#pragma unroll
            for (int fm = 0; fm < 4; fm++) {
#pragma unroll
                for (int fn = 0; fn < 4; fn++) {
                    int col = bx + wn + fn * 8 + ecol;
#pragma unroll
                    for (int half = 0; half < 2; half++) {
                        int row = by + wm + fm * 16 + erow + half * 8;
#pragma unroll
                        for (int e = 0; e < 2; e++) {
                            float vv = acc[fm][fn][half * 2 + e];
                            Vt16[(size_t)(col + e) * S + row] = __float2half_rn(vv);
                        }
                    }
                }
            }
        }
    }
}

// ---------------- fp16 1-term GEMM: O projection, static persistent ----------------
#define G16STAGE 16384u

__global__ __launch_bounds__(256, 2) void gemmo_kernel(
    const __half* __restrict__ A16, const __half* __restrict__ B16,
    float* __restrict__ Cf, int Ndim, int Kdim, int ntx, int ntiles)
{
    extern __shared__ char dsm[];
    const uint32_t smem = s2u(dsm);

    const int tid = threadIdx.x;
    const int wid = tid >> 5;
    const int lane = tid & 31;
    const int wm = (wid & 1) * 64;
    const int wn = (wid >> 1) * 32;
    const int grp = lane >> 3;
    const int ri = lane & 7;

    for (int tile = blockIdx.x; tile < ntiles; tile += gridDim.x) {
        const int bx = (tile % ntx) * 128;
        const int by = (tile / ntx) * 128;

        float acc[4][4][4];
#pragma unroll
        for (int i = 0; i < 4; i++)
#pragma unroll
            for (int j = 0; j < 4; j++)
#pragma unroll
                for (int e = 0; e < 4; e++) acc[i][j][e] = 0.0f;

        auto load_stage = [&](int c, int stage) {
            const uint32_t sb = smem + stage * G16STAGE;
            const int k0 = c << 5;
#pragma unroll
            for (int i = 0; i < 2; i++) {
                int idx = tid + i * 256;
                int row = idx >> 2, cc = idx & 3;
                uint32_t sc = (uint32_t)(cc ^ ((row >> 1) & 3));
                uint32_t so = (uint32_t)row * 64u + sc * 16u;
                cpasync16(sb + so, A16 + (size_t)(by + row) * Kdim + k0 + cc * 8);
                int brow = idx >> 4, bc = idx & 15;
                uint32_t bsc = (uint32_t)(bc ^ (brow & 15));
                cpasync16(sb + GTILE + (uint32_t)brow * 256u + bsc * 16u,
                          B16 + (size_t)(k0 + brow) * Ndim + bx + bc * 8);
            }
        };

        load_stage(0, 0);
        asm volatile("cp.async.commit_group;");
        load_stage(1, 1);
        asm volatile("cp.async.commit_group;");

        const int nchunks = Kdim >> 5;
        for (int c = 0; c < nchunks; c++) {
            if (c + 1 < nchunks) asm volatile("cp.async.wait_group 1;");
            else                 asm volatile("cp.async.wait_group 0;");
            __syncthreads();
            if (c + 2 < nchunks) {
                load_stage(c + 2, (c + 2) % 3);
                asm volatile("cp.async.commit_group;");
            }
            const uint32_t sb = smem + (c % 3) * G16STAGE;
#pragma unroll
            for (int k16 = 0; k16 < 2; k16++) {
                const int lchunk = k16 * 2 + (grp >> 1);
                uint32_t ah[4][4];
#pragma unroll
                for (int fm = 0; fm < 4; fm++) {
                    int row = wm + fm * 16 + (grp & 1) * 8 + ri;
                    uint32_t ad = sb + (uint32_t)row * 64u
                                + (uint32_t)((lchunk ^ ((row >> 1) & 3)) * 16);
                    ldmx4(ah[fm], ad);
                }
                const int krow = (k16 * 16) + (lane & 15);
#pragma unroll
                for (int fnp = 0; fnp < 2; fnp++) {
                    int ncol16 = ((wn + fnp * 16) >> 3) + (lane >> 4);
                    uint32_t bsc = (uint32_t)(ncol16 ^ (krow & 15));
                    uint32_t bd = sb + GTILE + (uint32_t)krow * 256u + bsc * 16u;
                    uint32_t bh4[4];
                    ldmx4t(bh4, bd);
                    uint32_t be[2] = {bh4[0], bh4[1]};
                    uint32_t bo[2] = {bh4[2], bh4[3]};
#pragma unroll
                    for (int fm = 0; fm < 4; fm++) {
                        mma16816h(acc[fm][2 * fnp],     ah[fm], be);
                        mma16816h(acc[fm][2 * fnp + 1], ah[fm], bo);
                    }
                }
            }
        }

        const int erow = lane >> 2;
        const int ecol = (lane & 3) * 2;
#pragma unroll
        for (int fm = 0; fm < 4; fm++) {
#pragma unroll
            for (int fn = 0; fn < 4; fn++) {
                float* cp0 = Cf + (size_t)(by + wm + fm * 16 + erow) * Ndim + bx + wn + fn * 8 + ecol;
                float* cp1 = cp0 + 8 * (size_t)Ndim;
                *reinterpret_cast<float2*>(cp0) = make_float2(acc[fm][fn][0], acc[fm][fn][1]);
                *reinterpret_cast<float2*>(cp1) = make_float2(acc[fm][fn][2], acc[fm][fn][3]);
            }
        }
        __syncthreads();
    }
}

// ---------------- flash attention: all-fp16, Q overlaid on K smem (unchanged) ----------------
#define KPAD 272u
#define VPAD 144u
#define SM_KH 0u
#define SM_KL 17408u
#define SM_V  34816u
#define SM_TOT 53248u

__global__ __launch_bounds__(128, 3) void fattn_kernel(
    const __half* __restrict__ Qh, const __half* __restrict__ Ql,
    const __half* __restrict__ Kh, const __half* __restrict__ Kl,
    const __half* __restrict__ Vt16, __half* __restrict__ O16)
{
    extern __shared__ char dsm[];
    const uint32_t smem = s2u(dsm);
    const int tid = threadIdx.x;
    const int wid = tid >> 5, lane = tid & 31;
    const int qt = gridDim.x - 1 - blockIdx.x;
    const int h = blockIdx.y;
    const int kvh = h / NREP;
    const int q0 = qt * 64;

    const int r = lane >> 2;
    const int cgrp = lane & 3;
    const int grp = lane >> 3;
    const int ri = lane & 7;

    auto loadK = [&](int t) {
#pragma unroll
        for (int i = 0; i < 8; i++) {
            int idx = tid + i * 128;
            int row = idx >> 4, cc = idx & 15;
            size_t g = (size_t)(t * 64 + row) * KVD + kvh * HD + cc * 8;
            cpasync16(smem + SM_KH + row * KPAD + cc * 16, Kh + g);
            cpasync16(smem + SM_KL + row * KPAD + cc * 16, Kl + g);
        }
    };
    auto loadV = [&](int t) {
#pragma unroll
        for (int i = 0; i < 8; i++) {
            int idx = tid + i * 128;
            int row = idx >> 3, cc = idx & 7;
            size_t g = (size_t)(kvh * HD + row) * S + t * 64 + cc * 8;
            cpasync16(smem + SM_V + row * VPAD + cc * 16, Vt16 + g);
        }
    };

#pragma unroll
    for (int i = 0; i < 8; i++) {
        int idx = tid + i * 128;
        int row = idx >> 4, cc = idx & 15;
        size_t g = (size_t)(q0 + row) * D + h * HD + cc * 8;
        cpasync16(smem + SM_KH + row * KPAD + cc * 16, Qh + g);
        cpasync16(smem + SM_KL + row * KPAD + cc * 16, Ql + g);
    }
    asm volatile("cp.async.commit_group;");
    asm volatile("cp.async.wait_group 0;");
    __syncthreads();

    uint32_t qh[8][4], ql[8][4];
    {
        int qrow = wid * 16 + (grp & 1) * 8 + ri;
        uint32_t qbase = smem + SM_KH + (uint32_t)qrow * KPAD + (grp >> 1) * 16u;
#pragma unroll
        for (int ks = 0; ks < 8; ks++) {
            ldmx4(qh[ks], qbase + ks * 32u);
            ldmx4(ql[ks], qbase + ks * 32u + (SM_KL - SM_KH));
        }
    }
    __syncthreads();

    loadK(0);
    asm volatile("cp.async.commit_group;");

    float m0 = -1e30f, m1 = -1e30f, l0 = 0.0f, l1 = 0.0f;
    float oacc[16][4];
#pragma unroll
    for (int f = 0; f < 16; f++)
#pragma unroll
        for (int e = 0; e < 4; e++) oacc[f][e] = 0.0f;

    const int rowA = wid * 16 + r;
    const int rowB = rowA + 8;

    for (int t = 0; t <= qt; t++) {
        asm volatile("cp.async.wait_group 0;");
        __syncthreads();
        loadV(t);
        asm volatile("cp.async.commit_group;");

        float sacc[8][4];
#pragma unroll
        for (int f = 0; f < 8; f++)
#pragma unroll
            for (int e = 0; e < 4; e++) sacc[f][e] = 0.0f;

#pragma unroll
        for (int ks = 0; ks < 8; ks++) {
#pragma unroll
            for (int fnp = 0; fnp < 4; fnp++) {
                int krow = fnp * 16 + (grp & 1) * 8 + ri;
                uint32_t ka = smem + SM_KH + (uint32_t)krow * KPAD + ks * 32u + (grp >> 1) * 16u;
                uint32_t bh4[4], bl4[4];
                ldmx4(bh4, ka);
                ldmx4(bl4, ka + (SM_KL - SM_KH));
                uint32_t be[2]  = {bh4[0], bh4[2]};
                uint32_t bo[2]  = {bh4[1], bh4[3]};
                uint32_t ble[2] = {bl4[0], bl4[2]};
                uint32_t blo[2] = {bl4[1], bl4[3]};
                mma16816h(sacc[2 * fnp],     qh[ks], be);
                mma16816h(sacc[2 * fnp],     ql[ks], be);
                mma16816h(sacc[2 * fnp],     qh[ks], ble);
                mma16816h(sacc[2 * fnp + 1], qh[ks], bo);
                mma16816h(sacc[2 * fnp + 1], ql[ks], bo);
                mma16816h(sacc[2 * fnp + 1], qh[ks], blo);
            }
        }

        if (t == qt) {
#pragma unroll
            for (int fn = 0; fn < 8; fn++) {
                int c0 = fn * 8 + cgrp * 2;
                if (c0 > rowA) sacc[fn][0] = -1e30f;
                if (c0 + 1 > rowA) sacc[fn][1] = -1e30f;
                if (c0 > rowB) sacc[fn][2] = -1e30f;
                if (c0 + 1 > rowB) sacc[fn][3] = -1e30f;
            }
        }

        float tm0 = -1e30f, tm1 = -1e30f;
#pragma unroll
        for (int fn = 0; fn < 8; fn++) {
            tm0 = fmaxf(tm0, fmaxf(sacc[fn][0], sacc[fn][1]));
            tm1 = fmaxf(tm1, fmaxf(sacc[fn][2], sacc[fn][3]));
        }
        tm0 = fmaxf(tm0, __shfl_xor_sync(0xFFFFFFFFu, tm0, 1));
        tm0 = fmaxf(tm0, __shfl_xor_sync(0xFFFFFFFFu, tm0, 2));
        tm1 = fmaxf(tm1, __shfl_xor_sync(0xFFFFFFFFu, tm1, 1));
        tm1 = fmaxf(tm1, __shfl_xor_sync(0xFFFFFFFFu, tm1, 2));

        float mn0 = fmaxf(m0, tm0), mn1 = fmaxf(m1, tm1);
        float corr0 = exp2f(m0 - mn0), corr1 = exp2f(m1 - mn1);
        m0 = mn0; m1 = mn1;

        float rs0 = 0.0f, rs1 = 0.0f;
#pragma unroll
        for (int fn = 0; fn < 8; fn++) {
            sacc[fn][0] = exp2f(sacc[fn][0] - m0);
            sacc[fn][1] = exp2f(sacc[fn][1] - m0);
            sacc[fn][2] = exp2f(sacc[fn][2] - m1);
            sacc[fn][3] = exp2f(sacc[fn][3] - m1);
            rs0 += sacc[fn][0] + sacc[fn][1];
            rs1 += sacc[fn][2] + sacc[fn][3];
        }
        rs0 += __shfl_xor_sync(0xFFFFFFFFu, rs0, 1);
        rs0 += __shfl_xor_sync(0xFFFFFFFFu, rs0, 2);
        rs1 += __shfl_xor_sync(0xFFFFFFFFu, rs1, 1);
        rs1 += __shfl_xor_sync(0xFFFFFFFFu, rs1, 2);
        l0 = l0 * corr0 + rs0;
        l1 = l1 * corr1 + rs1;

#pragma unroll
        for (int f = 0; f < 16; f++) {
            oacc[f][0] *= corr0; oacc[f][1] *= corr0;
            oacc[f][2] *= corr1; oacc[f][3] *= corr1;
        }

        asm volatile("cp.async.wait_group 0;");
        __syncthreads();
        if (t < qt) {
            loadK(t + 1);
            asm volatile("cp.async.commit_group;");
        }

#pragma unroll
        for (int kk = 0; kk < 4; kk++) {
            uint32_t aph[4];
#pragma unroll
            for (int half = 0; half < 2; half++) {
                const float* sp = sacc[2 * kk + half];
                aph[half * 2 + 0] = pack_f16(sp[0], sp[1]);
                aph[half * 2 + 1] = pack_f16(sp[2], sp[3]);
            }
#pragma unroll
            for (int fnp = 0; fnp < 8; fnp++) {
                int vrow = fnp * 16 + (grp & 1) * 8 + ri;
                uint32_t va = smem + SM_V + (uint32_t)vrow * VPAD + kk * 32u + (grp >> 1) * 16u;
                uint32_t bh4[4];
                ldmx4(bh4, va);
                uint32_t be[2] = {bh4[0], bh4[2]};
                uint32_t bo[2] = {bh4[1], bh4[3]};
                mma16816h(oacc[2 * fnp],     aph, be);
                mma16816h(oacc[2 * fnp + 1], aph, bo);
            }
        }
    }

    float inv0 = 1.0f / l0, inv1 = 1.0f / l1;
    const size_t gr0 = (size_t)(q0 + rowA) * D + h * HD + cgrp * 2;
    const size_t gr1 = (size_t)(q0 + rowB) * D + h * HD + cgrp * 2;
#pragma unroll
    for (int fn = 0; fn < 16; fn++) {
        *reinterpret_cast<__half2*>(O16 + gr0 + fn * 8) =
            __floats2half2_rn(oacc[fn][0] * inv0, oacc[fn][1] * inv0);
        *reinterpret_cast<__half2*>(O16 + gr1 + fn * 8) =
            __floats2half2_rn(oacc[fn][2] * inv1, oacc[fn][3] * inv1);
    }
}

// ---------------- launch ----------------
extern "C" void kernel_launch(void* const* d_in, const int* in_sizes, int n_in,
                              void* d_out, int out_size)
{
    const float* x    = (const float*)d_in[0];
    const float* wq   = (const float*)d_in[1];
    const float* wk   = (const float*)d_in[2];
    const float* wv   = (const float*)d_in[3];
    const float* wo   = (const float*)d_in[4];
    const float* cosb = (const float*)d_in[5];
    const float* sinb = (const float*)d_in[6];
    float* out = (float*)d_out;

    __half *x16h, *x16l, *a16, *q16h, *q16l, *k16h, *k16l, *vt16;
    __half *wq16, *wk16, *wv16, *wo16;
    cudaGetSymbolAddress((void**)&x16h, g_x16h); cudaGetSymbolAddress((void**)&x16l, g_x16l);
    cudaGetSymbolAddress((void**)&a16, g_a16);
    cudaGetSymbolAddress((void**)&q16h, g_q16h); cudaGetSymbolAddress((void**)&q16l, g_q16l);
    cudaGetSymbolAddress((void**)&k16h, g_k16h); cudaGetSymbolAddress((void**)&k16l, g_k16l);
    cudaGetSymbolAddress((void**)&vt16, g_vt16);
    cudaGetSymbolAddress((void**)&wq16, g_wq16); cudaGetSymbolAddress((void**)&wk16, g_wk16);
    cudaGetSymbolAddress((void**)&wv16, g_wv16); cudaGetSymbolAddress((void**)&wo16, g_wo16);

    const int shmem = 3 * (int)GSTAGE;        // 73728
    const int shmemo = 3 * (int)G16STAGE;     // 49152
    cudaFuncSetAttribute(proj_kernel, cudaFuncAttributeMaxDynamicSharedMemorySize, shmem);
    cudaFuncSetAttribute(gemmo_kernel, cudaFuncAttributeMaxDynamicSharedMemorySize, shmemo);
    cudaFuncSetAttribute(fattn_kernel, cudaFuncAttributeMaxDynamicSharedMemorySize, (int)SM_TOT);

    const float qscale = 0.08838834764831845f * 1.4426950408889634f;  // 1/sqrt(128)*log2(e)

    // input conversions (weights: pure streaming fp32->fp16, native [K,N] layout)
    xsplit16<<<(S * D / 4 + 255) / 256, 256>>>(x, x16h, x16l, S * D / 4);
    wconv16<<<(D * D / 4 + 255) / 256, 256>>>(wq, wq16, D * D / 4);
    wconv16<<<(D * KVD / 4 + 255) / 256, 256>>>(wk, wk16, D * KVD / 4);
    wconv16<<<(D * KVD / 4 + 255) / 256, 256>>>(wv, wv16, D * KVD / 4);
    wconv16<<<(D * D / 4 + 255) / 256, 256>>>(wo, wo16, D * D / 4);

    // unified Q/K/V projection, dynamic tile scheduler
    reset_ctr<<<1, 1>>>();
    proj_kernel<<<PGRID, 256, shmem>>>(
        x16h, x16l, wq16, wk16, wv16,
        q16h, q16l, k16h, k16l, vt16, cosb, sinb, qscale);

    // flash attention (log2-domain softmax, all fp16) -> fp16
    fattn_kernel<<<dim3(S / 64, H), 128, SM_TOT>>>(q16h, q16l, k16h, k16l, vt16, a16);

    // output projection: fp16 1-term, fp32 out, static persistent
    gemmo_kernel<<<PGRID, 256, shmemo>>>(
        a16, wo16, out, D, D, D / 128, (D / 128) * (S / 128));
}

// round 17
// speedup vs baseline: 1.1891x; 1.0186x over previous
#include <cuda_runtime.h>
#include <cuda_bf16.h>
#include <cuda_fp16.h>
#include <cstdint>

#define S 2048
#define D 4096
#define H 32
#define KVH 8
#define HD 128
#define NREP (H / KVH)
#define KVD (KVH * HD)
#define PGRID 304

// ---------------- scratch (static device arrays; no allocation) ----------------
__device__ __half g_x16h[S * D], g_x16l[S * D];
__device__ __half g_a16[S * D];
__device__ __half g_q16h[S * D], g_q16l[S * D];
__device__ __half g_k16h[S * KVD], g_k16l[S * KVD];
__device__ __half g_vt16[KVD * S];                 // transposed [KVD][S]
__device__ __half g_wq16[D * D];                   // native [K,N] fp16
__device__ __half g_wk16[D * KVD];
__device__ __half g_wv16[D * KVD];
__device__ __half g_wo16[D * D];
__device__ int    g_ctr;

// ---------------- helpers ----------------
__device__ __forceinline__ uint32_t s2u(const void* p) {
    uint32_t a;
    asm("{ .reg .u64 t; cvta.to.shared.u64 t, %1; cvt.u32.u64 %0, t; }" : "=r"(a) : "l"(p));
    return a;
}
__device__ __forceinline__ void cpasync16(uint32_t saddr, const void* gaddr) {
    asm volatile("cp.async.cg.shared.global [%0], [%1], 16;" :: "r"(saddr), "l"(gaddr));
}
__device__ __forceinline__ void ldmx4(uint32_t* r, uint32_t addr) {
    asm volatile("ldmatrix.sync.aligned.m8n8.x4.shared.b16 {%0,%1,%2,%3}, [%4];"
                 : "=r"(r[0]), "=r"(r[1]), "=r"(r[2]), "=r"(r[3]) : "r"(addr));
}
__device__ __forceinline__ void ldmx4t(uint32_t* r, uint32_t addr) {
    asm volatile("ldmatrix.sync.aligned.m8n8.x4.trans.shared.b16 {%0,%1,%2,%3}, [%4];"
                 : "=r"(r[0]), "=r"(r[1]), "=r"(r[2]), "=r"(r[3]) : "r"(addr));
}
__device__ __forceinline__ void mma16816h(float* d, const uint32_t* a, const uint32_t* b) {
    asm volatile(
        "mma.sync.aligned.m16n8k16.row.col.f32.f16.f16.f32 "
        "{%0,%1,%2,%3}, {%4,%5,%6,%7}, {%8,%9}, {%0,%1,%2,%3};"
        : "+f"(d[0]), "+f"(d[1]), "+f"(d[2]), "+f"(d[3])
        : "r"(a[0]), "r"(a[1]), "r"(a[2]), "r"(a[3]), "r"(b[0]), "r"(b[1]));
}
__device__ __forceinline__ uint32_t pack_f16(float x, float y) {
    __half2 t = __floats2half2_rn(x, y);
    return *reinterpret_cast<uint32_t*>(&t);
}
__device__ __forceinline__ void split2h(float v0, float v1, __half2& ph, __half2& pl) {
    __half h0 = __float2half_rn(v0), h1 = __float2half_rn(v1);
    ph = __halves2half2(h0, h1);
    pl = __halves2half2(__float2half_rn(v0 - __half2float(h0)),
                        __float2half_rn(v1 - __half2float(h1)));
}

// ---------------- counter reset ----------------
__global__ void reset_ctr() { g_ctr = 0; }

// ---------------- x: fp32 -> fp16 hi/lo ----------------
__global__ void xsplit16(const float* __restrict__ in,
                         __half* __restrict__ fh, __half* __restrict__ fl, int n4)
{
    int i = blockIdx.x * blockDim.x + threadIdx.x;
    if (i >= n4) return;
    float4 v = reinterpret_cast<const float4*>(in)[i];
    __half2 hh, hl;
    split2h(v.x, v.y, hh, hl);
    reinterpret_cast<__half2*>(fh)[2 * i] = hh;
    reinterpret_cast<__half2*>(fl)[2 * i] = hl;
    split2h(v.z, v.w, hh, hl);
    reinterpret_cast<__half2*>(fh)[2 * i + 1] = hh;
    reinterpret_cast<__half2*>(fl)[2 * i + 1] = hl;
}

// ---------------- streaming convert: fp32 -> fp16, same layout ----------------
__global__ void wconv16(const float* __restrict__ in, __half* __restrict__ out, int n4)
{
    int i = blockIdx.x * blockDim.x + threadIdx.x;
    if (i >= n4) return;
    float4 v = reinterpret_cast<const float4*>(in)[i];
    reinterpret_cast<__half2*>(out)[2 * i]     = __floats2half2_rn(v.x, v.y);
    reinterpret_cast<__half2*>(out)[2 * i + 1] = __floats2half2_rn(v.z, v.w);
}

#define GTILE  8192u
#define GSTAGE 24576u   // 3 tiles: A-hi, A-lo, B

// tile map: [0,128) K tiles, [128,640) Q tiles, [640,768) V tiles (1-term, light)
#define NT_K 128
#define NT_Q 512
#define NT_TOT 768

// ---------------- unified persistent projection kernel (all fp16) ----------------
__global__ __launch_bounds__(256, 2) void proj_kernel(
    const __half* __restrict__ X16h, const __half* __restrict__ X16l,
    const __half* __restrict__ Wq16, const __half* __restrict__ Wk16,
    const __half* __restrict__ Wv16,
    __half* __restrict__ Q16h, __half* __restrict__ Q16l,
    __half* __restrict__ K16h, __half* __restrict__ K16l,
    __half* __restrict__ Vt16,
    const float* __restrict__ cosb, const float* __restrict__ sinb, float qscale)
{
    extern __shared__ char dsm[];
    const uint32_t smem = s2u(dsm);
    __shared__ int s_tile;

    const int tid = threadIdx.x;
    const int wid = tid >> 5;
    const int lane = tid & 31;
    const int wm = (wid & 1) * 64;
    const int wn = (wid >> 1) * 32;
    const int grp = lane >> 3;
    const int ri = lane & 7;
    const int erow = lane >> 2;
    const int ecol = (lane & 3) * 2;
    const int nchunks = D >> 5;

    while (true) {
        __syncthreads();
        if (tid == 0) s_tile = atomicAdd(&g_ctr, 1);
        __syncthreads();
        const int t = s_tile;
        if (t >= NT_TOT) break;

        const bool isV = (t >= NT_K + NT_Q);
        const __half* B;
        __half *Ch = nullptr, *Cl = nullptr;
        int bx, by, Ndim = 0, Bn;
        float scale = 1.0f;
        if (t < NT_K) {
            B = Wk16; bx = (t & 7) * 128; by = (t >> 3) * 128;
            Ndim = KVD; Bn = KVD; Ch = K16h; Cl = K16l;
        } else if (!isV) {
            int q = t - NT_K;
            B = Wq16; bx = (q & 31) * 128; by = (q >> 5) * 128;
            Ndim = D; Bn = D; scale = qscale; Ch = Q16h; Cl = Q16l;
        } else {
            int v = t - NT_K - NT_Q;
            B = Wv16; bx = (v & 7) * 128; by = (v >> 3) * 128;
            Bn = KVD;
        }
        const bool two_term = !isV;

        float acc[4][4][4];
#pragma unroll
        for (int i = 0; i < 4; i++)
#pragma unroll
            for (int j = 0; j < 4; j++)
#pragma unroll
                for (int e = 0; e < 4; e++) acc[i][j][e] = 0.0f;

        auto load_stage = [&](int c, int stage) {
            const uint32_t sb = smem + stage * GSTAGE;
            const int k0 = c << 5;
#pragma unroll
            for (int i = 0; i < 2; i++) {
                int idx = tid + i * 256;
                int row = idx >> 2, cc = idx & 3;
                uint32_t sc = (uint32_t)(cc ^ ((row >> 1) & 3));
                uint32_t so = (uint32_t)row * 64u + sc * 16u;
                size_t ga = (size_t)(by + row) * D + k0 + cc * 8;
                cpasync16(sb + so, X16h + ga);
                if (two_term) cpasync16(sb + GTILE + so, X16l + ga);
                int brow = idx >> 4, bc = idx & 15;
                uint32_t bsc = (uint32_t)(bc ^ (brow & 15));
                cpasync16(sb + 2 * GTILE + (uint32_t)brow * 256u + bsc * 16u,
                          B + (size_t)(k0 + brow) * Bn + bx + bc * 8);
            }
        };

        load_stage(0, 0);
        asm volatile("cp.async.commit_group;");
        load_stage(1, 1);
        asm volatile("cp.async.commit_group;");

        for (int c = 0; c < nchunks; c++) {
            if (c + 1 < nchunks) asm volatile("cp.async.wait_group 1;");
            else                 asm volatile("cp.async.wait_group 0;");
            __syncthreads();
            if (c + 2 < nchunks) {
                load_stage(c + 2, (c + 2) % 3);
                asm volatile("cp.async.commit_group;");
            }
            const uint32_t sb = smem + (c % 3) * GSTAGE;

#pragma unroll
            for (int k16 = 0; k16 < 2; k16++) {
                const int lchunk = k16 * 2 + (grp >> 1);
                uint32_t ah[4][4], al[4][4];
#pragma unroll
                for (int fm = 0; fm < 4; fm++) {
                    int row = wm + fm * 16 + (grp & 1) * 8 + ri;
                    uint32_t ad = sb + (uint32_t)row * 64u
                                + (uint32_t)((lchunk ^ ((row >> 1) & 3)) * 16);
                    ldmx4(ah[fm], ad);
                    if (two_term) ldmx4(al[fm], ad + GTILE);
                }
                const int krow = (k16 * 16) + (lane & 15);
#pragma unroll
                for (int fnp = 0; fnp < 2; fnp++) {
                    int ncol16 = ((wn + fnp * 16) >> 3) + (lane >> 4);
                    uint32_t bsc = (uint32_t)(ncol16 ^ (krow & 15));
                    uint32_t bd = sb + 2 * GTILE + (uint32_t)krow * 256u + bsc * 16u;
                    uint32_t bh4[4];
                    ldmx4t(bh4, bd);
                    uint32_t be[2] = {bh4[0], bh4[1]};
                    uint32_t bo[2] = {bh4[2], bh4[3]};
#pragma unroll
                    for (int fm = 0; fm < 4; fm++) {
                        mma16816h(acc[fm][2 * fnp],     ah[fm], be);
                        mma16816h(acc[fm][2 * fnp + 1], ah[fm], bo);
                        if (two_term) {
                            mma16816h(acc[fm][2 * fnp],     al[fm], be);
                            mma16816h(acc[fm][2 * fnp + 1], al[fm], bo);
                        }
                    }
                }
            }
        }

        if (!isV) {
#pragma unroll
            for (int fm = 0; fm < 4; fm++) {
#pragma unroll
                for (int fn = 0; fn < 4; fn++) {
                    int col = bx + wn + fn * 8 + ecol;
                    int i = (col & 127) >> 1;
#pragma unroll
                    for (int half = 0; half < 2; half++) {
                        int row = by + wm + fm * 16 + erow + half * 8;
                        float cv = cosb[row * 64 + i];
                        float sv = sinb[row * 64 + i];
                        float t0 = acc[fm][fn][half * 2], t1 = acc[fm][fn][half * 2 + 1];
                        float o0 = (t0 * cv - t1 * sv) * scale;
                        float o1 = (t0 * sv + t1 * cv) * scale;
                        __half2 ph, pl;
                        split2h(o0, o1, ph, pl);
                        size_t o = (size_t)row * Ndim + col;
                        *reinterpret_cast<__half2*>(Ch + o) = ph;
                        *reinterpret_cast<__half2*>(Cl + o) = pl;
                    }
                }
            }
        } else {
#pragma unroll
            for (int fm = 0; fm < 4; fm++) {
#pragma unroll
                for (int fn = 0; fn < 4; fn++) {
                    int col = bx + wn + fn * 8 + ecol;
#pragma unroll
                    for (int half = 0; half < 2; half++) {
                        int row = by + wm + fm * 16 + erow + half * 8;
#pragma unroll
                        for (int e = 0; e < 2; e++) {
                            float vv = acc[fm][fn][half * 2 + e];
                            Vt16[(size_t)(col + e) * S + row] = __float2half_rn(vv);
                        }
                    }
                }
            }
        }
    }
}

// ---------------- fp16 1-term GEMM: O projection, static persistent ----------------
#define G16STAGE 16384u

__global__ __launch_bounds__(256, 2) void gemmo_kernel(
    const __half* __restrict__ A16, const __half* __restrict__ B16,
    float* __restrict__ Cf, int Ndim, int Kdim, int ntx, int ntiles)
{
    extern __shared__ char dsm[];
    const uint32_t smem = s2u(dsm);

    const int tid = threadIdx.x;
    const int wid = tid >> 5;
    const int lane = tid & 31;
    const int wm = (wid & 1) * 64;
    const int wn = (wid >> 1) * 32;
    const int grp = lane >> 3;
    const int ri = lane & 7;

    for (int tile = blockIdx.x; tile < ntiles; tile += gridDim.x) {
        const int bx = (tile % ntx) * 128;
        const int by = (tile / ntx) * 128;

        float acc[4][4][4];
#pragma unroll
        for (int i = 0; i < 4; i++)
#pragma unroll
            for (int j = 0; j < 4; j++)
#pragma unroll
                for (int e = 0; e < 4; e++) acc[i][j][e] = 0.0f;

        auto load_stage = [&](int c, int stage) {
            const uint32_t sb = smem + stage * G16STAGE;
            const int k0 = c << 5;
#pragma unroll
            for (int i = 0; i < 2; i++) {
                int idx = tid + i * 256;
                int row = idx >> 2, cc = idx & 3;
                uint32_t sc = (uint32_t)(cc ^ ((row >> 1) & 3));
                uint32_t so = (uint32_t)row * 64u + sc * 16u;
                cpasync16(sb + so, A16 + (size_t)(by + row) * Kdim + k0 + cc * 8);
                int brow = idx >> 4, bc = idx & 15;
                uint32_t bsc = (uint32_t)(bc ^ (brow & 15));
                cpasync16(sb + GTILE + (uint32_t)brow * 256u + bsc * 16u,
                          B16 + (size_t)(k0 + brow) * Ndim + bx + bc * 8);
            }
        };

        load_stage(0, 0);
        asm volatile("cp.async.commit_group;");
        load_stage(1, 1);
        asm volatile("cp.async.commit_group;");

        const int nchunks = Kdim >> 5;
        for (int c = 0; c < nchunks; c++) {
            if (c + 1 < nchunks) asm volatile("cp.async.wait_group 1;");
            else                 asm volatile("cp.async.wait_group 0;");
            __syncthreads();
            if (c + 2 < nchunks) {
                load_stage(c + 2, (c + 2) % 3);
                asm volatile("cp.async.commit_group;");
            }
            const uint32_t sb = smem + (c % 3) * G16STAGE;
#pragma unroll
            for (int k16 = 0; k16 < 2; k16++) {
                const int lchunk = k16 * 2 + (grp >> 1);
                uint32_t ah[4][4];
#pragma unroll
                for (int fm = 0; fm < 4; fm++) {
                    int row = wm + fm * 16 + (grp & 1) * 8 + ri;
                    uint32_t ad = sb + (uint32_t)row * 64u
                                + (uint32_t)((lchunk ^ ((row >> 1) & 3)) * 16);
                    ldmx4(ah[fm], ad);
                }
                const int krow = (k16 * 16) + (lane & 15);
#pragma unroll
                for (int fnp = 0; fnp < 2; fnp++) {
                    int ncol16 = ((wn + fnp * 16) >> 3) + (lane >> 4);
                    uint32_t bsc = (uint32_t)(ncol16 ^ (krow & 15));
                    uint32_t bd = sb + GTILE + (uint32_t)krow * 256u + bsc * 16u;
                    uint32_t bh4[4];
                    ldmx4t(bh4, bd);
                    uint32_t be[2] = {bh4[0], bh4[1]};
                    uint32_t bo[2] = {bh4[2], bh4[3]};
#pragma unroll
                    for (int fm = 0; fm < 4; fm++) {
                        mma16816h(acc[fm][2 * fnp],     ah[fm], be);
                        mma16816h(acc[fm][2 * fnp + 1], ah[fm], bo);
                    }
                }
            }
        }

        const int erow = lane >> 2;
        const int ecol = (lane & 3) * 2;
#pragma unroll
        for (int fm = 0; fm < 4; fm++) {
#pragma unroll
            for (int fn = 0; fn < 4; fn++) {
                float* cp0 = Cf + (size_t)(by + wm + fm * 16 + erow) * Ndim + bx + wn + fn * 8 + ecol;
                float* cp1 = cp0 + 8 * (size_t)Ndim;
                *reinterpret_cast<float2*>(cp0) = make_float2(acc[fm][fn][0], acc[fm][fn][1]);
                *reinterpret_cast<float2*>(cp1) = make_float2(acc[fm][fn][2], acc[fm][fn][3]);
            }
        }
        __syncthreads();
    }
}

// ---------------- flash attention: 128-KV tiles, all-fp16, Q staged through K smem ----------------
#define KPAD 272u
#define VPAD 272u
#define SM_KH 0u
#define SM_KL 34816u
#define SM_V  69632u
#define SM_TOT 104448u

__global__ __launch_bounds__(128, 2) void fattn_kernel(
    const __half* __restrict__ Qh, const __half* __restrict__ Ql,
    const __half* __restrict__ Kh, const __half* __restrict__ Kl,
    const __half* __restrict__ Vt16, __half* __restrict__ O16)
{
    extern __shared__ char dsm[];
    const uint32_t smem = s2u(dsm);
    const int tid = threadIdx.x;
    const int wid = tid >> 5, lane = tid & 31;
    const int qt = gridDim.x - 1 - blockIdx.x;   // long blocks first
    const int h = blockIdx.y;
    const int kvh = h / NREP;
    const int q0 = qt * 64;

    const int r = lane >> 2;
    const int cgrp = lane & 3;
    const int grp = lane >> 3;
    const int ri = lane & 7;

    // 128-kv tiles covering [0, q0+64)
    const int nt = (q0 >> 7) + 1;

    auto loadK = [&](int t) {
#pragma unroll
        for (int i = 0; i < 16; i++) {
            int idx = tid + i * 128;
            int row = idx >> 4, cc = idx & 15;     // 128 kv rows x 16 units
            size_t g = (size_t)(t * 128 + row) * KVD + kvh * HD + cc * 8;
            cpasync16(smem + SM_KH + row * KPAD + cc * 16, Kh + g);
            cpasync16(smem + SM_KL + row * KPAD + cc * 16, Kl + g);
        }
    };
    auto loadV = [&](int t) {
#pragma unroll
        for (int i = 0; i < 16; i++) {
            int idx = tid + i * 128;
            int row = idx >> 4, cc = idx & 15;     // 128 hd rows x 16 units
            size_t g = (size_t)(kvh * HD + row) * S + t * 128 + cc * 8;
            cpasync16(smem + SM_V + row * VPAD + cc * 16, Vt16 + g);
        }
    };

    // ---- stage Q (64 rows) into K region, read to registers, release ----
#pragma unroll
    for (int i = 0; i < 8; i++) {
        int idx = tid + i * 128;
        int row = idx >> 4, cc = idx & 15;
        size_t g = (size_t)(q0 + row) * D + h * HD + cc * 8;
        cpasync16(smem + SM_KH + row * KPAD + cc * 16, Qh + g);
        cpasync16(smem + SM_KL + row * KPAD + cc * 16, Ql + g);
    }
    asm volatile("cp.async.commit_group;");
    asm volatile("cp.async.wait_group 0;");
    __syncthreads();

    uint32_t qh[8][4], ql[8][4];
    {
        int qrow = wid * 16 + (grp & 1) * 8 + ri;
        uint32_t qbase = smem + SM_KH + (uint32_t)qrow * KPAD + (grp >> 1) * 16u;
#pragma unroll
        for (int ks = 0; ks < 8; ks++) {
            ldmx4(qh[ks], qbase + ks * 32u);
            ldmx4(ql[ks], qbase + ks * 32u + (SM_KL - SM_KH));
        }
    }
    __syncthreads();

    loadK(0);
    asm volatile("cp.async.commit_group;");

    float m0 = -1e30f, m1 = -1e30f, l0 = 0.0f, l1 = 0.0f;
    float oacc[16][4];
#pragma unroll
    for (int f = 0; f < 16; f++)
#pragma unroll
        for (int e = 0; e < 4; e++) oacc[f][e] = 0.0f;

    const int rowA = wid * 16 + r;
    const int rowB = rowA + 8;

    for (int t = 0; t < nt; t++) {
        asm volatile("cp.async.wait_group 0;");
        __syncthreads();
        loadV(t);
        asm volatile("cp.async.commit_group;");

        float sacc[16][4];
#pragma unroll
        for (int f = 0; f < 16; f++)
#pragma unroll
            for (int e = 0; e < 4; e++) sacc[f][e] = 0.0f;

#pragma unroll
        for (int ks = 0; ks < 8; ks++) {
#pragma unroll
            for (int fnp = 0; fnp < 8; fnp++) {
                int krow = fnp * 16 + (grp & 1) * 8 + ri;
                uint32_t ka = smem + SM_KH + (uint32_t)krow * KPAD + ks * 32u + (grp >> 1) * 16u;
                uint32_t bh4[4], bl4[4];
                ldmx4(bh4, ka);
                ldmx4(bl4, ka + (SM_KL - SM_KH));
                uint32_t be[2]  = {bh4[0], bh4[2]};
                uint32_t bo[2]  = {bh4[1], bh4[3]};
                uint32_t ble[2] = {bl4[0], bl4[2]};
                uint32_t blo[2] = {bl4[1], bl4[3]};
                mma16816h(sacc[2 * fnp],     qh[ks], be);
                mma16816h(sacc[2 * fnp],     ql[ks], be);
                mma16816h(sacc[2 * fnp],     qh[ks], ble);
                mma16816h(sacc[2 * fnp + 1], qh[ks], bo);
                mma16816h(sacc[2 * fnp + 1], ql[ks], bo);
                mma16816h(sacc[2 * fnp + 1], qh[ks], blo);
            }
        }

        // causal mask on last tile (global col > global row)
        if (t == nt - 1) {
            const int kb = (nt - 1) * 128;
#pragma unroll
            for (int fn = 0; fn < 16; fn++) {
                int c0 = kb + fn * 8 + cgrp * 2;
                if (c0 > q0 + rowA) sacc[fn][0] = -1e30f;
                if (c0 + 1 > q0 + rowA) sacc[fn][1] = -1e30f;
                if (c0 > q0 + rowB) sacc[fn][2] = -1e30f;
                if (c0 + 1 > q0 + rowB) sacc[fn][3] = -1e30f;
            }
        }

        float tm0 = -1e30f, tm1 = -1e30f;
#pragma unroll
        for (int fn = 0; fn < 16; fn++) {
            tm0 = fmaxf(tm0, fmaxf(sacc[fn][0], sacc[fn][1]));
            tm1 = fmaxf(tm1, fmaxf(sacc[fn][2], sacc[fn][3]));
        }
        tm0 = fmaxf(tm0, __shfl_xor_sync(0xFFFFFFFFu, tm0, 1));
        tm0 = fmaxf(tm0, __shfl_xor_sync(0xFFFFFFFFu, tm0, 2));
        tm1 = fmaxf(tm1, __shfl_xor_sync(0xFFFFFFFFu, tm1, 1));
        tm1 = fmaxf(tm1, __shfl_xor_sync(0xFFFFFFFFu, tm1, 2));

        float mn0 = fmaxf(m0, tm0), mn1 = fmaxf(m1, tm1);
        float corr0 = exp2f(m0 - mn0), corr1 = exp2f(m1 - mn1);
        m0 = mn0; m1 = mn1;

        float rs0 = 0.0f, rs1 = 0.0f;
#pragma unroll
        for (int fn = 0; fn < 16; fn++) {
            sacc[fn][0] = exp2f(sacc[fn][0] - m0);
            sacc[fn][1] = exp2f(sacc[fn][1] - m0);
            sacc[fn][2] = exp2f(sacc[fn][2] - m1);
            sacc[fn][3] = exp2f(sacc[fn][3] - m1);
            rs0 += sacc[fn][0] + sacc[fn][1];
            rs1 += sacc[fn][2] + sacc[fn][3];
        }
        rs0 += __shfl_xor_sync(0xFFFFFFFFu, rs0, 1);
        rs0 += __shfl_xor_sync(0xFFFFFFFFu, rs0, 2);
        rs1 += __shfl_xor_sync(0xFFFFFFFFu, rs1, 1);
        rs1 += __shfl_xor_sync(0xFFFFFFFFu, rs1, 2);
        l0 = l0 * corr0 + rs0;
        l1 = l1 * corr1 + rs1;

#pragma unroll
        for (int f = 0; f < 16; f++) {
            oacc[f][0] *= corr0; oacc[f][1] *= corr0;
            oacc[f][2] *= corr1; oacc[f][3] *= corr1;
        }

        asm volatile("cp.async.wait_group 0;");
        __syncthreads();
        if (t + 1 < nt) {
            loadK(t + 1);
            asm volatile("cp.async.commit_group;");
        }

        // ---- O += P V ----
#pragma unroll
        for (int kk = 0; kk < 8; kk++) {
            uint32_t aph[4];
#pragma unroll
            for (int half = 0; half < 2; half++) {
                const float* sp = sacc[2 * kk + half];
                aph[half * 2 + 0] = pack_f16(sp[0], sp[1]);
                aph[half * 2 + 1] = pack_f16(sp[2], sp[3]);
            }
#pragma unroll
            for (int fnp = 0; fnp < 8; fnp++) {
                int vrow = fnp * 16 + (grp & 1) * 8 + ri;
                uint32_t va = smem + SM_V + (uint32_t)vrow * VPAD + kk * 32u + (grp >> 1) * 16u;
                uint32_t bh4[4];
                ldmx4(bh4, va);
                uint32_t be[2] = {bh4[0], bh4[2]};
                uint32_t bo[2] = {bh4[1], bh4[3]};
                mma16816h(oacc[2 * fnp],     aph, be);
                mma16816h(oacc[2 * fnp + 1], aph, bo);
            }
        }
    }

    float inv0 = 1.0f / l0, inv1 = 1.0f / l1;
    const size_t gr0 = (size_t)(q0 + rowA) * D + h * HD + cgrp * 2;
    const size_t gr1 = (size_t)(q0 + rowB) * D + h * HD + cgrp * 2;
#pragma unroll
    for (int fn = 0; fn < 16; fn++) {
        *reinterpret_cast<__half2*>(O16 + gr0 + fn * 8) =
            __floats2half2_rn(oacc[fn][0] * inv0, oacc[fn][1] * inv0);
        *reinterpret_cast<__half2*>(O16 + gr1 + fn * 8) =
            __floats2half2_rn(oacc[fn][2] * inv1, oacc[fn][3] * inv1);
    }
}

// ---------------- launch ----------------
extern "C" void kernel_launch(void* const* d_in, const int* in_sizes, int n_in,
                              void* d_out, int out_size)
{
    const float* x    = (const float*)d_in[0];
    const float* wq   = (const float*)d_in[1];
    const float* wk   = (const float*)d_in[2];
    const float* wv   = (const float*)d_in[3];
    const float* wo   = (const float*)d_in[4];
    const float* cosb = (const float*)d_in[5];
    const float* sinb = (const float*)d_in[6];
    float* out = (float*)d_out;

    __half *x16h, *x16l, *a16, *q16h, *q16l, *k16h, *k16l, *vt16;
    __half *wq16, *wk16, *wv16, *wo16;
    cudaGetSymbolAddress((void**)&x16h, g_x16h); cudaGetSymbolAddress((void**)&x16l, g_x16l);
    cudaGetSymbolAddress((void**)&a16, g_a16);
    cudaGetSymbolAddress((void**)&q16h, g_q16h); cudaGetSymbolAddress((void**)&q16l, g_q16l);
    cudaGetSymbolAddress((void**)&k16h, g_k16h); cudaGetSymbolAddress((void**)&k16l, g_k16l);
    cudaGetSymbolAddress((void**)&vt16, g_vt16);
    cudaGetSymbolAddress((void**)&wq16, g_wq16); cudaGetSymbolAddress((void**)&wk16, g_wk16);
    cudaGetSymbolAddress((void**)&wv16, g_wv16); cudaGetSymbolAddress((void**)&wo16, g_wo16);

    const int shmem = 3 * (int)GSTAGE;        // 73728
    const int shmemo = 3 * (int)G16STAGE;     // 49152
    cudaFuncSetAttribute(proj_kernel, cudaFuncAttributeMaxDynamicSharedMemorySize, shmem);
    cudaFuncSetAttribute(gemmo_kernel, cudaFuncAttributeMaxDynamicSharedMemorySize, shmemo);
    cudaFuncSetAttribute(fattn_kernel, cudaFuncAttributeMaxDynamicSharedMemorySize, (int)SM_TOT);

    const float qscale = 0.08838834764831845f * 1.4426950408889634f;  // 1/sqrt(128)*log2(e)

    // input conversions
    xsplit16<<<(S * D / 4 + 255) / 256, 256>>>(x, x16h, x16l, S * D / 4);
    wconv16<<<(D * D / 4 + 255) / 256, 256>>>(wq, wq16, D * D / 4);
    wconv16<<<(D * KVD / 4 + 255) / 256, 256>>>(wk, wk16, D * KVD / 4);
    wconv16<<<(D * KVD / 4 + 255) / 256, 256>>>(wv, wv16, D * KVD / 4);
    wconv16<<<(D * D / 4 + 255) / 256, 256>>>(wo, wo16, D * D / 4);

    // unified Q/K/V projection, dynamic tile scheduler
    reset_ctr<<<1, 1>>>();
    proj_kernel<<<PGRID, 256, shmem>>>(
        x16h, x16l, wq16, wk16, wv16,
        q16h, q16l, k16h, k16l, vt16, cosb, sinb, qscale);

    // flash attention (128-kv tiles, log2-domain softmax) -> fp16
    fattn_kernel<<<dim3(S / 64, H), 128, SM_TOT>>>(q16h, q16l, k16h, k16l, vt16, a16);

    // output projection: fp16 1-term, fp32 out, static persistent
    gemmo_kernel<<<PGRID, 256, shmemo>>>(
        a16, wo16, out, D, D, D / 128, (D / 128) * (S / 128));
}